// round 2
// baseline (speedup 1.0000x reference)
#include <cuda_runtime.h>
#include <cstddef>

#define NN   100000
#define NPAD 100096   // 782 * 128
#define EE   1600000

// ---------------- scratch (device globals; no allocation allowed) ----------------
__device__ __align__(16) float g_h  [(size_t)NPAD * 128];
__device__ __align__(16) float g_agg[(size_t)NPAD * 128];
__device__ __align__(16) float g_t1 [(size_t)NPAD * 256];
__device__ __align__(16) float g_hc [(size_t)NPAD * 128];
__device__ __align__(16) float g_sum1[256];
__device__ __align__(16) float g_sq1 [256];
__device__ __align__(16) float g_sum2[128];
__device__ __align__(16) float g_sq2 [128];
__device__ __align__(16) float g_a1[256];
__device__ __align__(16) float g_c1[256];
__device__ __align__(16) float g_a2[128];
__device__ __align__(16) float g_c2[128];

// ---------------- helpers ----------------
__device__ __forceinline__ void red_add_v4(float* p, float a, float b, float c, float d) {
    asm volatile("red.global.add.v4.f32 [%0], {%1,%2,%3,%4};"
                 :: "l"(p), "f"(a), "f"(b), "f"(c), "f"(d) : "memory");
}

// ---------------- h0 = sum_f atom_emb[f][x[:,f]] + z_emb[z] ----------------
__global__ void embed_kernel(const int* __restrict__ x, const int* __restrict__ z,
                             const float* __restrict__ atom, const float* __restrict__ zemb) {
    int gid = blockIdx.x * blockDim.x + threadIdx.x;
    int node = gid >> 5;
    if (node >= NN) return;
    int c = (gid & 31) * 4;
    const int* xr = x + node * 9;
    float4 acc = *(const float4*)&zemb[(size_t)z[node] * 128 + c];
#pragma unroll
    for (int f = 0; f < 9; f++) {
        int idx = xr[f];
        float4 v = *(const float4*)&atom[((size_t)(f * 119 + idx)) * 128 + c];
        acc.x += v.x; acc.y += v.y; acc.z += v.z; acc.w += v.w;
    }
    *(float4*)&g_h[(size_t)node * 128 + c] = acc;
}

// ---------------- zero agg + BN stat accumulators ----------------
__global__ void zero_kernel() {
    int gid = blockIdx.x * blockDim.x + threadIdx.x;
    if (gid < NN * 32)
        *(float4*)&g_agg[(size_t)gid * 4] = make_float4(0.f, 0.f, 0.f, 0.f);
    if (gid < 256) { g_sum1[gid] = 0.f; g_sq1[gid] = 0.f; }
    if (gid < 128) { g_sum2[gid] = 0.f; g_sq2[gid] = 0.f; }
}

// ---------------- edge kernel: agg[dst] += relu(h[src] + bond_emb(edge_attr)) ----------------
__global__ void edge_kernel(const int* __restrict__ ei, const int* __restrict__ ea,
                            const float* __restrict__ bt) {
    int gid = blockIdx.x * blockDim.x + threadIdx.x;
    int e = gid >> 5;
    if (e >= EE) return;
    int c = (gid & 31) * 4;
    int src = ei[e];
    int dst = ei[EE + e];
    int a0 = ea[e * 3 + 0], a1 = ea[e * 3 + 1], a2 = ea[e * 3 + 2];
    float4 h4 = *(const float4*)&g_h[(size_t)src * 128 + c];
    float4 b0 = *(const float4*)&bt[(size_t)(0 * 6 + a0) * 128 + c];
    float4 b1 = *(const float4*)&bt[(size_t)(1 * 6 + a1) * 128 + c];
    float4 b2 = *(const float4*)&bt[(size_t)(2 * 6 + a2) * 128 + c];
    float vx = fmaxf(h4.x + b0.x + b1.x + b2.x, 0.f);
    float vy = fmaxf(h4.y + b0.y + b1.y + b2.y, 0.f);
    float vz = fmaxf(h4.z + b0.z + b1.z + b2.z, 0.f);
    float vw = fmaxf(h4.w + b0.w + b1.w + b2.w, 0.f);
    red_add_v4(&g_agg[(size_t)dst * 128 + c], vx, vy, vz, vw);
}

// ---------------- fused SGEMM ----------------
// MODE 0: A = (1+eps)*g_h + g_agg  [N,128];  C = A @ W1 + b1 -> g_t1 [N,256]
// MODE 1: A = relu(g_t1 * a1 + c1) [N,256];  C = A @ W2 + b2 -> g_hc [N,128]
template <int MODE>
__global__ __launch_bounds__(256) void gemm_kernel(const float* __restrict__ B,
                                                   const float* __restrict__ bias,
                                                   const float* __restrict__ epsp) {
    constexpr int KT   = (MODE == 0) ? 128 : 256;
    constexpr int NCOL = (MODE == 0) ? 256 : 128;
    __shared__ __align__(16) float As[16][132];
    __shared__ __align__(16) float Bs[16][128];

    int t = threadIdx.x;
    int blockRow = blockIdx.x * 128;
    int c0 = blockIdx.y * 128;
    float epsv = 1.f;
    if (MODE == 0) epsv = 1.f + epsp[0];

    float acc[8][8];
#pragma unroll
    for (int i = 0; i < 8; i++)
#pragma unroll
        for (int j = 0; j < 8; j++) acc[i][j] = 0.f;

    int tx = t & 15, ty = t >> 4;

    for (int kt = 0; kt < KT / 16; kt++) {
        // stage A tile (transposed), with fused producer transform
#pragma unroll
        for (int i = 0; i < 2; i++) {
            int v = t + i * 256;
            int row = v >> 2;
            int kq = (v & 3) * 4;
            int r = blockRow + row;
            int kg = kt * 16 + kq;
            float4 a = make_float4(0.f, 0.f, 0.f, 0.f);
            if (r < NN) {
                if (MODE == 0) {
                    float4 hv = *(const float4*)&g_h[(size_t)r * 128 + kg];
                    float4 av = *(const float4*)&g_agg[(size_t)r * 128 + kg];
                    a.x = epsv * hv.x + av.x; a.y = epsv * hv.y + av.y;
                    a.z = epsv * hv.z + av.z; a.w = epsv * hv.w + av.w;
                } else {
                    float4 tv = *(const float4*)&g_t1[(size_t)r * 256 + kg];
                    float4 sc = *(const float4*)&g_a1[kg];
                    float4 sh = *(const float4*)&g_c1[kg];
                    a.x = fmaxf(tv.x * sc.x + sh.x, 0.f);
                    a.y = fmaxf(tv.y * sc.y + sh.y, 0.f);
                    a.z = fmaxf(tv.z * sc.z + sh.z, 0.f);
                    a.w = fmaxf(tv.w * sc.w + sh.w, 0.f);
                }
            }
            As[kq + 0][row] = a.x; As[kq + 1][row] = a.y;
            As[kq + 2][row] = a.z; As[kq + 3][row] = a.w;
        }
        // stage B tile
#pragma unroll
        for (int i = 0; i < 2; i++) {
            int v = t + i * 256;
            int kr = v >> 5;
            int cq = (v & 31) * 4;
            *(float4*)&Bs[kr][cq] =
                *(const float4*)&B[(size_t)(kt * 16 + kr) * NCOL + c0 + cq];
        }
        __syncthreads();
#pragma unroll
        for (int kk = 0; kk < 16; kk++) {
            float4 a0v = *(const float4*)&As[kk][ty * 8];
            float4 a1v = *(const float4*)&As[kk][ty * 8 + 4];
            float4 b0v = *(const float4*)&Bs[kk][tx * 8];
            float4 b1v = *(const float4*)&Bs[kk][tx * 8 + 4];
            float ar[8] = {a0v.x, a0v.y, a0v.z, a0v.w, a1v.x, a1v.y, a1v.z, a1v.w};
            float br[8] = {b0v.x, b0v.y, b0v.z, b0v.w, b1v.x, b1v.y, b1v.z, b1v.w};
#pragma unroll
            for (int i = 0; i < 8; i++)
#pragma unroll
                for (int j = 0; j < 8; j++)
                    acc[i][j] += ar[i] * br[j];
        }
        __syncthreads();
    }
    float* Cout = (MODE == 0) ? g_t1 : g_hc;
    float4 bb0 = *(const float4*)&bias[c0 + tx * 8];
    float4 bb1 = *(const float4*)&bias[c0 + tx * 8 + 4];
#pragma unroll
    for (int i = 0; i < 8; i++) {
        size_t off = (size_t)(blockRow + ty * 8 + i) * NCOL + c0 + tx * 8;
        float4 o0 = make_float4(acc[i][0] + bb0.x, acc[i][1] + bb0.y,
                                acc[i][2] + bb0.z, acc[i][3] + bb0.w);
        float4 o1 = make_float4(acc[i][4] + bb1.x, acc[i][5] + bb1.y,
                                acc[i][6] + bb1.z, acc[i][7] + bb1.w);
        *(float4*)&Cout[off] = o0;
        *(float4*)&Cout[off + 4] = o1;
    }
}

// ---------------- column sums / sums of squares ----------------
template <int WHICH>
__global__ void colstats_kernel() {
    constexpr int C = (WHICH == 0) ? 256 : 128;
    const float* X = (WHICH == 0) ? g_t1 : g_hc;
    float* S = (WHICH == 0) ? g_sum1 : g_sum2;
    float* Q = (WHICH == 0) ? g_sq1 : g_sq2;
    constexpr int RPB = 256 / C;
    int col = threadIdx.x % C;
    int ro  = threadIdx.x / C;
    float s = 0.f, q = 0.f;
    for (int r = blockIdx.x * RPB + ro; r < NN; r += gridDim.x * RPB) {
        float v = X[(size_t)r * C + col];
        s += v; q += v * v;
    }
    atomicAdd(&S[col], s);
    atomicAdd(&Q[col], q);
}

// ---------------- finalize BN affine: a = g/sqrt(var+eps), b = beta - mean*a ----------------
template <int WHICH>
__global__ void finalize_kernel(const float* __restrict__ gamma,
                                const float* __restrict__ beta) {
    constexpr int C = (WHICH == 0) ? 256 : 128;
    int c = threadIdx.x;
    if (c >= C) return;
    float s = (WHICH == 0) ? g_sum1[c] : g_sum2[c];
    float q = (WHICH == 0) ? g_sq1[c]  : g_sq2[c];
    float mean = s * (1.f / NN);
    float var  = q * (1.f / NN) - mean * mean;
    float inv  = rsqrtf(var + 1e-5f);
    float a = gamma[c] * inv;
    float b = beta[c] - mean * a;
    if (WHICH == 0) { g_a1[c] = a; g_c1[c] = b; }
    else            { g_a2[c] = a; g_c2[c] = b; }
}

// ---------------- apply final BN (+optional relu), write to g_h or d_out ----------------
__global__ void bnapply_kernel(float* __restrict__ dst, int do_relu) {
    int gid = blockIdx.x * blockDim.x + threadIdx.x;
    int node = gid >> 5;
    if (node >= NN) return;
    int c = (gid & 31) * 4;
    float4 v = *(const float4*)&g_hc[(size_t)node * 128 + c];
    float4 a = *(const float4*)&g_a2[c];
    float4 b = *(const float4*)&g_c2[c];
    float4 o;
    o.x = v.x * a.x + b.x; o.y = v.y * a.y + b.y;
    o.z = v.z * a.z + b.z; o.w = v.w * a.w + b.w;
    if (do_relu) {
        o.x = fmaxf(o.x, 0.f); o.y = fmaxf(o.y, 0.f);
        o.z = fmaxf(o.z, 0.f); o.w = fmaxf(o.w, 0.f);
    }
    float* d = dst ? dst : g_h;
    *(float4*)&d[(size_t)node * 128 + c] = o;
}

// ---------------- launch ----------------
extern "C" void kernel_launch(void* const* d_in, const int* in_sizes, int n_in,
                              void* d_out, int out_size) {
    const int*   x    = (const int*)d_in[0];
    const int*   z    = (const int*)d_in[1];
    const int*   ei   = (const int*)d_in[2];
    const int*   ea   = (const int*)d_in[3];
    const float* atom = (const float*)d_in[4];
    const float* zemb = (const float*)d_in[5];
    const float* bond = (const float*)d_in[6];
    const float* eps  = (const float*)d_in[7];
    const float* W1   = (const float*)d_in[8];
    const float* b1   = (const float*)d_in[9];
    const float* g1   = (const float*)d_in[10];
    const float* be1  = (const float*)d_in[11];
    const float* W2   = (const float*)d_in[12];
    const float* b2   = (const float*)d_in[13];
    const float* bng  = (const float*)d_in[14];
    const float* bnb  = (const float*)d_in[15];
    float* out = (float*)d_out;

    const int NODE_BLKS = (NN * 32 + 255) / 256;
    const int EDGE_BLKS = (EE * 32 + 255) / 256;

    embed_kernel<<<NODE_BLKS, 256>>>(x, z, atom, zemb);
    for (int l = 0; l < 2; l++) {
        zero_kernel<<<NODE_BLKS, 256>>>();
        edge_kernel<<<EDGE_BLKS, 256>>>(ei, ea, bond + (size_t)l * 3 * 6 * 128);
        gemm_kernel<0><<<dim3(NPAD / 128, 2), 256>>>(W1 + (size_t)l * 128 * 256,
                                                     b1 + l * 256, eps + l);
        colstats_kernel<0><<<888, 256>>>();
        finalize_kernel<0><<<1, 256>>>(g1 + l * 256, be1 + l * 256);
        gemm_kernel<1><<<dim3(NPAD / 128, 1), 256>>>(W2 + (size_t)l * 256 * 128,
                                                     b2 + l * 128, nullptr);
        colstats_kernel<1><<<888, 256>>>();
        finalize_kernel<1><<<1, 128>>>(bng + l * 128, bnb + l * 128);
        bnapply_kernel<<<NODE_BLKS, 256>>>((l == 0) ? nullptr : out, (l == 0) ? 1 : 0);
    }
}

// round 4
// speedup vs baseline: 1.0676x; 1.0676x over previous
#include <cuda_runtime.h>
#include <cuda_bf16.h>
#include <cstddef>
#include <cstdint>

#define NN   100000
#define NPAD 100096   // 782 * 128
#define EE   1600000

// ---------------- scratch (device globals; no allocation allowed) ----------------
__device__ __align__(16) float g_h  [(size_t)NPAD * 128];
__device__ __align__(16) float g_agg[(size_t)NPAD * 128];
__device__ __align__(16) float g_t1 [(size_t)NPAD * 256];
__device__ __align__(16) float g_hc [(size_t)NPAD * 128];
__device__ __align__(16) float g_sum1[256];
__device__ __align__(16) float g_sq1 [256];
__device__ __align__(16) float g_sum2[128];
__device__ __align__(16) float g_sq2 [128];
__device__ __align__(16) float g_a1[256];
__device__ __align__(16) float g_c1[256];
__device__ __align__(16) float g_a2[128];
__device__ __align__(16) float g_c2[128];

// ---------------- helpers ----------------
__device__ __forceinline__ void red_add_v4(float* p, float a, float b, float c, float d) {
    asm volatile("red.global.add.v4.f32 [%0], {%1,%2,%3,%4};"
                 :: "l"(p), "f"(a), "f"(b), "f"(c), "f"(d) : "memory");
}

__device__ __forceinline__ uint32_t smem_u32(const void* p) {
    uint32_t a;
    asm("{ .reg .u64 t; cvta.to.shared.u64 t, %1; cvt.u32.u64 %0, t; }" : "=r"(a) : "l"(p));
    return a;
}

__device__ __forceinline__ void ldsm_x4(uint32_t (&r)[4], uint32_t addr) {
    asm volatile("ldmatrix.sync.aligned.m8n8.x4.shared.b16 {%0,%1,%2,%3}, [%4];"
                 : "=r"(r[0]), "=r"(r[1]), "=r"(r[2]), "=r"(r[3]) : "r"(addr));
}

__device__ __forceinline__ void ldsm_x2_t(uint32_t (&r)[2], uint32_t addr) {
    asm volatile("ldmatrix.sync.aligned.m8n8.x2.trans.shared.b16 {%0,%1}, [%2];"
                 : "=r"(r[0]), "=r"(r[1]) : "r"(addr));
}

__device__ __forceinline__ void mma16816(float (&d)[4], const uint32_t (&a)[4],
                                         const uint32_t (&b)[2]) {
    asm volatile("mma.sync.aligned.m16n8k16.row.col.f32.bf16.bf16.f32 "
                 "{%0,%1,%2,%3}, {%4,%5,%6,%7}, {%8,%9}, {%0,%1,%2,%3};"
                 : "+f"(d[0]), "+f"(d[1]), "+f"(d[2]), "+f"(d[3])
                 : "r"(a[0]), "r"(a[1]), "r"(a[2]), "r"(a[3]), "r"(b[0]), "r"(b[1]));
}

// 128B-row XOR swizzle (also correct for 256B rows w.r.t. the (row&7)<<4 unit XOR)
__device__ __forceinline__ uint32_t sw128(uint32_t off) {
    return off ^ ((off >> 3) & 0x70);
}

// split fp32 pair -> packed bf16x2 hi + bf16x2 lo
__device__ __forceinline__ void split2(float x, float y, uint32_t& hi, uint32_t& lo) {
    __nv_bfloat162 h = __floats2bfloat162_rn(x, y);
    float hx = __low2float(h), hy = __high2float(h);
    __nv_bfloat162 l = __floats2bfloat162_rn(x - hx, y - hy);
    hi = *reinterpret_cast<uint32_t*>(&h);
    lo = *reinterpret_cast<uint32_t*>(&l);
}

// ---------------- h0 = sum_f atom_emb[f][x[:,f]] + z_emb[z] ----------------
__global__ void embed_kernel(const int* __restrict__ x, const int* __restrict__ z,
                             const float* __restrict__ atom, const float* __restrict__ zemb) {
    int gid = blockIdx.x * blockDim.x + threadIdx.x;
    int node = gid >> 5;
    if (node >= NN) return;
    int c = (gid & 31) * 4;
    const int* xr = x + node * 9;
    float4 acc = *(const float4*)&zemb[(size_t)z[node] * 128 + c];
#pragma unroll
    for (int f = 0; f < 9; f++) {
        int idx = xr[f];
        float4 v = *(const float4*)&atom[((size_t)(f * 119 + idx)) * 128 + c];
        acc.x += v.x; acc.y += v.y; acc.z += v.z; acc.w += v.w;
    }
    *(float4*)&g_h[(size_t)node * 128 + c] = acc;
}

// ---------------- zero agg + BN stat accumulators ----------------
__global__ void zero_kernel() {
    int gid = blockIdx.x * blockDim.x + threadIdx.x;
    if (gid < NN * 32)
        *(float4*)&g_agg[(size_t)gid * 4] = make_float4(0.f, 0.f, 0.f, 0.f);
    if (gid < 256) { g_sum1[gid] = 0.f; g_sq1[gid] = 0.f; }
    if (gid < 128) { g_sum2[gid] = 0.f; g_sq2[gid] = 0.f; }
}

// ---------------- edge kernel: agg[dst] += relu(h[src] + bond_emb(edge_attr)) ----------------
__global__ void edge_kernel(const int* __restrict__ ei, const int* __restrict__ ea,
                            const float* __restrict__ bt) {
    int gid = blockIdx.x * blockDim.x + threadIdx.x;
    int e = gid >> 5;
    if (e >= EE) return;
    int c = (gid & 31) * 4;
    int src = ei[e];
    int dst = ei[EE + e];
    int a0 = ea[e * 3 + 0], a1 = ea[e * 3 + 1], a2 = ea[e * 3 + 2];
    float4 h4 = *(const float4*)&g_h[(size_t)src * 128 + c];
    float4 b0 = *(const float4*)&bt[(size_t)(0 * 6 + a0) * 128 + c];
    float4 b1 = *(const float4*)&bt[(size_t)(1 * 6 + a1) * 128 + c];
    float4 b2 = *(const float4*)&bt[(size_t)(2 * 6 + a2) * 128 + c];
    float vx = fmaxf(h4.x + b0.x + b1.x + b2.x, 0.f);
    float vy = fmaxf(h4.y + b0.y + b1.y + b2.y, 0.f);
    float vz = fmaxf(h4.z + b0.z + b1.z + b2.z, 0.f);
    float vw = fmaxf(h4.w + b0.w + b1.w + b2.w, 0.f);
    red_add_v4(&g_agg[(size_t)dst * 128 + c], vx, vy, vz, vw);
}

// ---------------- mma.sync bf16-split GEMM with fused BN column stats ----------------
// CTA tile 128x128, 8 warps (2x4), warp tile 64x32, K chunked by 64.
// 3 split terms: Ahi*Bhi + Ahi*Blo + Alo*Bhi (fp32 accumulate, lo*lo ~2^-18 dropped).
// MODE 0: A = (1+eps)*g_h + g_agg  [N,128]; C = A@W1 + b1 -> g_t1 [N,256] (grid.y=2)
// MODE 1: A = relu(g_t1*a1 + c1)   [N,256]; C = A@W2 + b2 -> g_hc [N,128] (grid.y=1)
// Epilogue also accumulates per-column sum/sumsq (rows < NN) into g_sum*/g_sq*.

#define GEMM_SMEM 65536

template <int MODE>
__global__ __launch_bounds__(256, 2) void gemm_mma(const float* __restrict__ W,
                                                   const float* __restrict__ bias,
                                                   const float* __restrict__ epsp) {
    constexpr int KTOT   = (MODE == 0) ? 128 : 256;
    constexpr int NCHUNK = KTOT / 64;
    constexpr int NCOL   = (MODE == 0) ? 256 : 128;

    extern __shared__ char smem[];
    uint32_t sbase = smem_u32(smem);
    // layout: A_hi [128x64 bf16, 128B rows] @0, A_lo @16384,
    //         B_hi [64k x 128n bf16, 256B rows] @32768, B_lo @49152
    uint32_t Au   = sbase;
    uint32_t Alou = sbase + 16384;
    uint32_t Bu   = sbase + 32768;
    uint32_t Blou = sbase + 49152;
    char* A_hi_p = smem;
    char* A_lo_p = smem + 16384;
    char* B_hi_p = smem + 32768;
    char* B_lo_p = smem + 49152;

    int t = threadIdx.x;
    int lane = t & 31;
    int wid = t >> 5;
    int wm = wid & 1;        // 0..1 -> 64-row block
    int wn = wid >> 1;       // 0..3 -> 32-col block
    int blockRow = blockIdx.x * 128;
    int c0 = blockIdx.y * 128;
    float epsv = 0.f;
    if constexpr (MODE == 0) epsv = 1.f + epsp[0];

    // staging maps
    int arow  = t >> 1;            // 0..127
    int acol0 = (t & 1) * 32;      // 0/32
    int bkrow = t >> 2;            // 0..63  (k within chunk)
    int bnseg = (t & 3) * 32;      // 0/32/64/96

    // mma lane address precompute
    int a_r  = wm * 64 + (lane & 7) + ((lane >> 3) & 1) * 8;   // row before mi*16
    int a_kh = (lane >> 4) * 8;                                // 0/8
    uint32_t swa = (uint32_t)((a_r & 7) << 4);
    int bl   = lane & 15;
    int b_k7 = bl & 7;
    int b_kh = ((bl >> 3) & 1) * 8;
    uint32_t swb = (uint32_t)(b_k7 << 4);
    uint32_t nboff[4];
#pragma unroll
    for (int ni = 0; ni < 4; ni++)
        nboff[ni] = ((uint32_t)((wn * 32 + ni * 8) * 2)) ^ swb;

    float acc[4][4][4];
#pragma unroll
    for (int mi = 0; mi < 4; mi++)
#pragma unroll
        for (int ni = 0; ni < 4; ni++)
#pragma unroll
            for (int j = 0; j < 4; j++) acc[mi][ni][j] = 0.f;

    for (int kc = 0; kc < NCHUNK; kc++) {
        int k0g = kc * 64;
        // ---- stage A chunk [128 rows x 64 k] (hi/lo), 128B rows, swizzled ----
        {
            size_t r = (size_t)(blockRow + arow);
#pragma unroll
            for (int q = 0; q < 8; q++) {
                int cl = acol0 + q * 4;
                int kg = k0g + cl;
                float4 a;
                if constexpr (MODE == 0) {
                    float4 hv = *(const float4*)&g_h[r * 128 + kg];
                    float4 av = *(const float4*)&g_agg[r * 128 + kg];
                    a.x = fmaf(epsv, hv.x, av.x); a.y = fmaf(epsv, hv.y, av.y);
                    a.z = fmaf(epsv, hv.z, av.z); a.w = fmaf(epsv, hv.w, av.w);
                } else {
                    float4 tv = *(const float4*)&g_t1[r * 256 + kg];
                    float4 sc = *(const float4*)&g_a1[kg];
                    float4 sh = *(const float4*)&g_c1[kg];
                    a.x = fmaxf(fmaf(tv.x, sc.x, sh.x), 0.f);
                    a.y = fmaxf(fmaf(tv.y, sc.y, sh.y), 0.f);
                    a.z = fmaxf(fmaf(tv.z, sc.z, sh.z), 0.f);
                    a.w = fmaxf(fmaf(tv.w, sc.w, sh.w), 0.f);
                }
                uint32_t h01, l01, h23, l23;
                split2(a.x, a.y, h01, l01);
                split2(a.z, a.w, h23, l23);
                uint32_t off = sw128((uint32_t)(arow * 128 + cl * 2));
                *(uint2*)(A_hi_p + off) = make_uint2(h01, h23);
                *(uint2*)(A_lo_p + off) = make_uint2(l01, l23);
            }
        }
        // ---- stage B chunk as [k][n] (hi/lo), 256B rows, swizzled ----
        {
#pragma unroll
            for (int q = 0; q < 8; q++) {
                int n = bnseg + q * 4;
                float4 w = *(const float4*)&W[(size_t)(k0g + bkrow) * NCOL + c0 + n];
                uint32_t h01, l01, h23, l23;
                split2(w.x, w.y, h01, l01);
                split2(w.z, w.w, h23, l23);
                uint32_t off = (uint32_t)(bkrow * 256) +
                               (((uint32_t)(n * 2)) ^ ((uint32_t)((bkrow & 7) << 4)));
                *(uint2*)(B_hi_p + off) = make_uint2(h01, h23);
                *(uint2*)(B_lo_p + off) = make_uint2(l01, l23);
            }
        }
        __syncthreads();

        // ---- mma: 3 terms x 4 k16-steps ----
#pragma unroll
        for (int term = 0; term < 3; term++) {
            uint32_t Ab = (term == 2) ? Alou : Au;
            uint32_t Bb = (term == 1) ? Blou : Bu;
#pragma unroll
            for (int kk = 0; kk < 4; kk++) {
                int k0 = kk * 16;
                uint32_t a[4][4];
                uint32_t b[4][2];
                uint32_t kA = (((uint32_t)((k0 + a_kh) * 2)) ^ swa);
#pragma unroll
                for (int mi = 0; mi < 4; mi++)
                    ldsm_x4(a[mi], Ab + (uint32_t)((a_r + mi * 16) * 128) + kA);
                uint32_t kB = (uint32_t)((k0 + b_kh + b_k7) * 256);
#pragma unroll
                for (int ni = 0; ni < 4; ni++)
                    ldsm_x2_t(b[ni], Bb + kB + nboff[ni]);
#pragma unroll
                for (int mi = 0; mi < 4; mi++)
#pragma unroll
                    for (int ni = 0; ni < 4; ni++)
                        mma16816(acc[mi][ni], a[mi], b[ni]);
            }
        }
        __syncthreads();
    }

    // ---- epilogue: bias add, store C, fused column stats ----
    float* s_s = (float*)smem;         // 128 floats
    float* s_q = (float*)smem + 128;   // 128 floats
    if (t < 128) { s_s[t] = 0.f; s_q[t] = 0.f; }
    __syncthreads();

    float* Cout = (MODE == 0) ? g_t1 : g_hc;
    int gidl = lane >> 2, tq = lane & 3;
    int colbase = wn * 32 + tq * 2;
    float2 bv[4];
#pragma unroll
    for (int ni = 0; ni < 4; ni++)
        bv[ni] = *(const float2*)&bias[c0 + colbase + ni * 8];

    float ssum[4][2] = {}, qsum[4][2] = {};
#pragma unroll
    for (int mi = 0; mi < 4; mi++) {
        int r0 = blockRow + wm * 64 + mi * 16 + gidl;
        int r1 = r0 + 8;
        bool ok0 = r0 < NN, ok1 = r1 < NN;
#pragma unroll
        for (int ni = 0; ni < 4; ni++) {
            float v0 = acc[mi][ni][0] + bv[ni].x;
            float v1 = acc[mi][ni][1] + bv[ni].y;
            float v2 = acc[mi][ni][2] + bv[ni].x;
            float v3 = acc[mi][ni][3] + bv[ni].y;
            int col = c0 + colbase + ni * 8;
            if (ok0) {
                *(float2*)&Cout[(size_t)r0 * NCOL + col] = make_float2(v0, v1);
                ssum[ni][0] += v0; qsum[ni][0] += v0 * v0;
                ssum[ni][1] += v1; qsum[ni][1] += v1 * v1;
            }
            if (ok1) {
                *(float2*)&Cout[(size_t)r1 * NCOL + col] = make_float2(v2, v3);
                ssum[ni][0] += v2; qsum[ni][0] += v2 * v2;
                ssum[ni][1] += v3; qsum[ni][1] += v3 * v3;
            }
        }
    }
#pragma unroll
    for (int ni = 0; ni < 4; ni++) {
        int cl = colbase + ni * 8;
        atomicAdd(&s_s[cl], ssum[ni][0]);
        atomicAdd(&s_s[cl + 1], ssum[ni][1]);
        atomicAdd(&s_q[cl], qsum[ni][0]);
        atomicAdd(&s_q[cl + 1], qsum[ni][1]);
    }
    __syncthreads();
    if (t < 128) {
        float* Sg = (MODE == 0) ? g_sum1 : g_sum2;
        float* Qg = (MODE == 0) ? g_sq1 : g_sq2;
        atomicAdd(&Sg[c0 + t], s_s[t]);
        atomicAdd(&Qg[c0 + t], s_q[t]);
    }
}

// ---------------- finalize BN affine: a = g/sqrt(var+eps), b = beta - mean*a ----------------
template <int WHICH>
__global__ void finalize_kernel(const float* __restrict__ gamma,
                                const float* __restrict__ beta) {
    constexpr int C = (WHICH == 0) ? 256 : 128;
    int c = threadIdx.x;
    if (c >= C) return;
    float s = (WHICH == 0) ? g_sum1[c] : g_sum2[c];
    float q = (WHICH == 0) ? g_sq1[c]  : g_sq2[c];
    float mean = s * (1.f / NN);
    float var  = q * (1.f / NN) - mean * mean;
    float inv  = rsqrtf(var + 1e-5f);
    float a = gamma[c] * inv;
    float b = beta[c] - mean * a;
    if (WHICH == 0) { g_a1[c] = a; g_c1[c] = b; }
    else            { g_a2[c] = a; g_c2[c] = b; }
}

// ---------------- apply final BN (+optional relu), write to g_h or d_out ----------------
__global__ void bnapply_kernel(float* __restrict__ dst, int do_relu) {
    int gid = blockIdx.x * blockDim.x + threadIdx.x;
    int node = gid >> 5;
    if (node >= NN) return;
    int c = (gid & 31) * 4;
    float4 v = *(const float4*)&g_hc[(size_t)node * 128 + c];
    float4 a = *(const float4*)&g_a2[c];
    float4 b = *(const float4*)&g_c2[c];
    float4 o;
    o.x = v.x * a.x + b.x; o.y = v.y * a.y + b.y;
    o.z = v.z * a.z + b.z; o.w = v.w * a.w + b.w;
    if (do_relu) {
        o.x = fmaxf(o.x, 0.f); o.y = fmaxf(o.y, 0.f);
        o.z = fmaxf(o.z, 0.f); o.w = fmaxf(o.w, 0.f);
    }
    float* d = dst ? dst : g_h;
    *(float4*)&d[(size_t)node * 128 + c] = o;
}

// ---------------- launch ----------------
extern "C" void kernel_launch(void* const* d_in, const int* in_sizes, int n_in,
                              void* d_out, int out_size) {
    const int*   x    = (const int*)d_in[0];
    const int*   z    = (const int*)d_in[1];
    const int*   ei   = (const int*)d_in[2];
    const int*   ea   = (const int*)d_in[3];
    const float* atom = (const float*)d_in[4];
    const float* zemb = (const float*)d_in[5];
    const float* bond = (const float*)d_in[6];
    const float* eps  = (const float*)d_in[7];
    const float* W1   = (const float*)d_in[8];
    const float* b1   = (const float*)d_in[9];
    const float* g1   = (const float*)d_in[10];
    const float* be1  = (const float*)d_in[11];
    const float* W2   = (const float*)d_in[12];
    const float* b2   = (const float*)d_in[13];
    const float* bng  = (const float*)d_in[14];
    const float* bnb  = (const float*)d_in[15];
    float* out = (float*)d_out;

    static bool attr_done = false;
    if (!attr_done) {
        cudaFuncSetAttribute(gemm_mma<0>, cudaFuncAttributeMaxDynamicSharedMemorySize, GEMM_SMEM);
        cudaFuncSetAttribute(gemm_mma<1>, cudaFuncAttributeMaxDynamicSharedMemorySize, GEMM_SMEM);
        attr_done = true;
    }

    const int NODE_BLKS = (NN * 32 + 255) / 256;
    const int EDGE_BLKS = (EE * 32 + 255) / 256;

    embed_kernel<<<NODE_BLKS, 256>>>(x, z, atom, zemb);
    for (int l = 0; l < 2; l++) {
        zero_kernel<<<NODE_BLKS, 256>>>();
        edge_kernel<<<EDGE_BLKS, 256>>>(ei, ea, bond + (size_t)l * 3 * 6 * 128);
        gemm_mma<0><<<dim3(NPAD / 128, 2), 256, GEMM_SMEM>>>(W1 + (size_t)l * 128 * 256,
                                                             b1 + l * 256, eps + l);
        finalize_kernel<0><<<1, 256>>>(g1 + l * 256, be1 + l * 256);
        gemm_mma<1><<<dim3(NPAD / 128, 1), 256, GEMM_SMEM>>>(W2 + (size_t)l * 256 * 128,
                                                             b2 + l * 128, eps + l);
        finalize_kernel<1><<<1, 128>>>(bng + l * 128, bnb + l * 128);
        bnapply_kernel<<<NODE_BLKS, 256>>>((l == 0) ? nullptr : out, (l == 0) ? 1 : 0);
    }
}

// round 6
// speedup vs baseline: 1.1146x; 1.0440x over previous
#include <cuda_runtime.h>
#include <cuda_bf16.h>
#include <cstddef>
#include <cstdint>

#define NN   100000
#define NPAD 100096   // 782 * 128
#define EE   1600000

// ---------------- scratch (device globals; no allocation allowed) ----------------
__device__ __align__(16) float g_h  [(size_t)NPAD * 128];
__device__ __align__(16) float g_agg[(size_t)NPAD * 128];
__device__ __align__(16) float g_t1 [(size_t)NPAD * 256];
__device__ __align__(16) float g_hc [(size_t)NPAD * 128];
__device__ __align__(16) float g_sum1[256];
__device__ __align__(16) float g_sq1 [256];
__device__ __align__(16) float g_sum2[128];
__device__ __align__(16) float g_sq2 [128];
__device__ __align__(16) float g_a1[256];
__device__ __align__(16) float g_c1[256];
__device__ __align__(16) float g_a2[128];
__device__ __align__(16) float g_c2[128];

// ---------------- helpers ----------------
__device__ __forceinline__ void red_add_v4(float* p, float a, float b, float c, float d) {
    asm volatile("red.global.add.v4.f32 [%0], {%1,%2,%3,%4};"
                 :: "l"(p), "f"(a), "f"(b), "f"(c), "f"(d) : "memory");
}

__device__ __forceinline__ uint32_t smem_u32(const void* p) {
    uint32_t a;
    asm("{ .reg .u64 t; cvta.to.shared.u64 t, %1; cvt.u32.u64 %0, t; }" : "=r"(a) : "l"(p));
    return a;
}

__device__ __forceinline__ void ldsm_x4(uint32_t (&r)[4], uint32_t addr) {
    asm volatile("ldmatrix.sync.aligned.m8n8.x4.shared.b16 {%0,%1,%2,%3}, [%4];"
                 : "=r"(r[0]), "=r"(r[1]), "=r"(r[2]), "=r"(r[3]) : "r"(addr));
}

__device__ __forceinline__ void ldsm_x2_t(uint32_t (&r)[2], uint32_t addr) {
    asm volatile("ldmatrix.sync.aligned.m8n8.x2.trans.shared.b16 {%0,%1}, [%2];"
                 : "=r"(r[0]), "=r"(r[1]) : "r"(addr));
}

__device__ __forceinline__ void mma16816(float (&d)[4], const uint32_t (&a)[4],
                                         const uint32_t (&b)[2]) {
    asm volatile("mma.sync.aligned.m16n8k16.row.col.f32.bf16.bf16.f32 "
                 "{%0,%1,%2,%3}, {%4,%5,%6,%7}, {%8,%9}, {%0,%1,%2,%3};"
                 : "+f"(d[0]), "+f"(d[1]), "+f"(d[2]), "+f"(d[3])
                 : "r"(a[0]), "r"(a[1]), "r"(a[2]), "r"(a[3]), "r"(b[0]), "r"(b[1]));
}

__device__ __forceinline__ uint32_t sw128(uint32_t off) {
    return off ^ ((off >> 3) & 0x70);
}

// split fp32 pair -> packed bf16x2 hi + bf16x2 lo
__device__ __forceinline__ void split2(float x, float y, uint32_t& hi, uint32_t& lo) {
    __nv_bfloat162 h = __floats2bfloat162_rn(x, y);
    float hx = __low2float(h), hy = __high2float(h);
    __nv_bfloat162 l = __floats2bfloat162_rn(x - hx, y - hy);
    hi = *reinterpret_cast<uint32_t*>(&h);
    lo = *reinterpret_cast<uint32_t*>(&l);
}

// ---------------- h0 = sum_f atom_emb[f][x[:,f]] + z_emb[z] ----------------
__global__ void embed_kernel(const int* __restrict__ x, const int* __restrict__ z,
                             const float* __restrict__ atom, const float* __restrict__ zemb) {
    int gid = blockIdx.x * blockDim.x + threadIdx.x;
    int node = gid >> 5;
    if (node >= NN) return;
    int c = (gid & 31) * 4;
    const int* xr = x + node * 9;
    float4 acc = *(const float4*)&zemb[(size_t)z[node] * 128 + c];
#pragma unroll
    for (int f = 0; f < 9; f++) {
        int idx = xr[f];
        float4 v = *(const float4*)&atom[((size_t)(f * 119 + idx)) * 128 + c];
        acc.x += v.x; acc.y += v.y; acc.z += v.z; acc.w += v.w;
    }
    *(float4*)&g_h[(size_t)node * 128 + c] = acc;
}

// ---------------- zero agg + BN stat accumulators ----------------
__global__ void zero_kernel() {
    int gid = blockIdx.x * blockDim.x + threadIdx.x;
    if (gid < NN * 32)
        *(float4*)&g_agg[(size_t)gid * 4] = make_float4(0.f, 0.f, 0.f, 0.f);
    if (gid < 256) { g_sum1[gid] = 0.f; g_sq1[gid] = 0.f; }
    if (gid < 128) { g_sum2[gid] = 0.f; g_sq2[gid] = 0.f; }
}

// ---------------- edge kernel: agg[dst] += relu(h[src] + bond_emb(edge_attr)) ----------------
__global__ void edge_kernel(const int* __restrict__ ei, const int* __restrict__ ea,
                            const float* __restrict__ bt) {
    int gid = blockIdx.x * blockDim.x + threadIdx.x;
    int e = gid >> 5;
    if (e >= EE) return;
    int c = (gid & 31) * 4;
    int src = ei[e];
    int dst = ei[EE + e];
    int a0 = ea[e * 3 + 0], a1 = ea[e * 3 + 1], a2 = ea[e * 3 + 2];
    float4 h4 = *(const float4*)&g_h[(size_t)src * 128 + c];
    float4 b0 = *(const float4*)&bt[(size_t)(0 * 6 + a0) * 128 + c];
    float4 b1 = *(const float4*)&bt[(size_t)(1 * 6 + a1) * 128 + c];
    float4 b2 = *(const float4*)&bt[(size_t)(2 * 6 + a2) * 128 + c];
    float vx = fmaxf(h4.x + b0.x + b1.x + b2.x, 0.f);
    float vy = fmaxf(h4.y + b0.y + b1.y + b2.y, 0.f);
    float vz = fmaxf(h4.z + b0.z + b1.z + b2.z, 0.f);
    float vw = fmaxf(h4.w + b0.w + b1.w + b2.w, 0.f);
    red_add_v4(&g_agg[(size_t)dst * 128 + c], vx, vy, vz, vw);
}

// ---------------- mma.sync bf16-split GEMM, pipelined, fused BN column stats ----------------
// CTA tile 128x128, 512 threads, 16 warps (4 row x 4 col), warp tile 32x32.
// K chunked by 64; register-prefetch + double-buffered smem (2 x 64KB stages).
// 3 split terms: Ahi*Bhi + Ahi*Blo + Alo*Bhi (fp32 accum; lo*lo ~2^-18 dropped).
// MODE 0: A = (1+eps)*g_h + g_agg  [N,128]; C = A@W1 + b1 -> g_t1 [N,256] (grid.y=2)
// MODE 1: A = relu(g_t1*a1 + c1)   [N,256]; C = A@W2 + b2 -> g_hc [N,128] (grid.y=1)
// Epilogue accumulates per-column sum/sumsq (rows < NN) into g_sum*/g_sq*.

#define STAGE_BYTES 65536
#define GEMM_SMEM   (2 * STAGE_BYTES + 2048)   // + a1/c1 staging for MODE1

template <int MODE>
__global__ __launch_bounds__(512, 1) void gemm_mma(const float* __restrict__ W,
                                                   const float* __restrict__ bias,
                                                   const float* __restrict__ epsp) {
    constexpr int KTOT   = (MODE == 0) ? 128 : 256;
    constexpr int NCHUNK = KTOT / 64;
    constexpr int NCOL   = (MODE == 0) ? 256 : 128;

    extern __shared__ char smem[];
    uint32_t sbase = smem_u32(smem);
    float* s_a1 = (float*)(smem + 2 * STAGE_BYTES);         // 256 floats (MODE1)
    float* s_c1 = (float*)(smem + 2 * STAGE_BYTES + 1024);  // 256 floats (MODE1)

    int t = threadIdx.x;
    int lane = t & 31;
    int wid = t >> 5;
    int wm = wid & 3;        // 0..3 -> 32-row block
    int wn = wid >> 2;       // 0..3 -> 32-col block
    int blockRow = blockIdx.x * 128;
    int c0 = blockIdx.y * 128;
    float epsv = 0.f;
    if constexpr (MODE == 0) epsv = 1.f + epsp[0];

    if constexpr (MODE == 1) {
        if (t < 256) { s_a1[t] = g_a1[t]; s_c1[t] = g_c1[t]; }
        __syncthreads();   // s_a1/s_c1 visible to ALL threads before STORE(0,0)
    }

    // staging maps (512 threads; A: 128x64, B: 64x128 per chunk)
    int arow = t >> 2;             // 0..127
    int ac0  = (t & 3) * 16;       // 0,16,32,48
    int bkr  = t >> 3;             // 0..63
    int bn0  = (t & 7) * 16;       // 0..112

    // mma lane addressing
    int a_r  = wm * 32 + (lane & 15);
    int a_kh = (lane >> 4) * 8;
    uint32_t swa = (uint32_t)((a_r & 7) << 4);
    int bl   = lane & 15;
    int b_k7 = bl & 7;
    int b_kh = ((bl >> 3) & 1) * 8;
    uint32_t nboff[4];
#pragma unroll
    for (int ni = 0; ni < 4; ni++)
        nboff[ni] = ((uint32_t)((wn * 32 + ni * 8) * 2)) ^ ((uint32_t)(b_k7 << 4));

    float acc[2][4][4];
#pragma unroll
    for (int mi = 0; mi < 2; mi++)
#pragma unroll
        for (int ni = 0; ni < 4; ni++)
#pragma unroll
            for (int j = 0; j < 4; j++) acc[mi][ni][j] = 0.f;

    float4 hA[4], aA[4], wB[4];   // prefetch registers (aA unused in MODE1)

    auto LOADA = [&](int kc) {
        size_t r = (size_t)(blockRow + arow);
        int kg = kc * 64 + ac0;
#pragma unroll
        for (int q = 0; q < 4; q++) {
            if constexpr (MODE == 0) {
                hA[q] = *(const float4*)&g_h[r * 128 + kg + q * 4];
                aA[q] = *(const float4*)&g_agg[r * 128 + kg + q * 4];
            } else {
                hA[q] = *(const float4*)&g_t1[r * 256 + kg + q * 4];
            }
        }
    };
    auto LOADB = [&](int kc) {
#pragma unroll
        for (int q = 0; q < 4; q++)
            wB[q] = *(const float4*)&W[(size_t)(kc * 64 + bkr) * NCOL + c0 + bn0 + q * 4];
    };
    auto STORE = [&](int s, int kc) {
        char* Ah = smem + s * STAGE_BYTES;
        char* Al = Ah + 16384;
        char* Bh = Ah + 32768;
        char* Bl = Ah + 49152;
#pragma unroll
        for (int q = 0; q < 4; q++) {
            int cl = ac0 + q * 4;
            float4 a;
            if constexpr (MODE == 0) {
                a.x = fmaf(epsv, hA[q].x, aA[q].x);
                a.y = fmaf(epsv, hA[q].y, aA[q].y);
                a.z = fmaf(epsv, hA[q].z, aA[q].z);
                a.w = fmaf(epsv, hA[q].w, aA[q].w);
            } else {
                int kg = kc * 64 + cl;
                float4 sc = *(const float4*)&s_a1[kg];
                float4 sh = *(const float4*)&s_c1[kg];
                a.x = fmaxf(fmaf(hA[q].x, sc.x, sh.x), 0.f);
                a.y = fmaxf(fmaf(hA[q].y, sc.y, sh.y), 0.f);
                a.z = fmaxf(fmaf(hA[q].z, sc.z, sh.z), 0.f);
                a.w = fmaxf(fmaf(hA[q].w, sc.w, sh.w), 0.f);
            }
            uint32_t h01, l01, h23, l23;
            split2(a.x, a.y, h01, l01);
            split2(a.z, a.w, h23, l23);
            uint32_t off = sw128((uint32_t)(arow * 128 + cl * 2));
            *(uint2*)(Ah + off) = make_uint2(h01, h23);
            *(uint2*)(Al + off) = make_uint2(l01, l23);
        }
#pragma unroll
        for (int q = 0; q < 4; q++) {
            int n = bn0 + q * 4;
            uint32_t h01, l01, h23, l23;
            split2(wB[q].x, wB[q].y, h01, l01);
            split2(wB[q].z, wB[q].w, h23, l23);
            uint32_t off = (uint32_t)(bkr * 256) +
                           (((uint32_t)(n * 2)) ^ ((uint32_t)((bkr & 7) << 4)));
            *(uint2*)(Bh + off) = make_uint2(h01, h23);
            *(uint2*)(Bl + off) = make_uint2(l01, l23);
        }
    };
    auto MMA = [&](int s) {
        uint32_t Au   = sbase + s * STAGE_BYTES;
        uint32_t Alou = Au + 16384;
        uint32_t Bu   = Au + 32768;
        uint32_t Blou = Au + 49152;
#pragma unroll
        for (int term = 0; term < 3; term++) {
            uint32_t Ab = (term == 2) ? Alou : Au;
            uint32_t Bb = (term == 1) ? Blou : Bu;
#pragma unroll
            for (int kk = 0; kk < 4; kk++) {
                int k0 = kk * 16;
                uint32_t a[2][4];
                uint32_t b[4][2];
                uint32_t kA = (((uint32_t)((k0 + a_kh) * 2)) ^ swa);
#pragma unroll
                for (int mi = 0; mi < 2; mi++)
                    ldsm_x4(a[mi], Ab + (uint32_t)((a_r + mi * 16) * 128) + kA);
                uint32_t kB = (uint32_t)((k0 + b_kh + b_k7) * 256);
#pragma unroll
                for (int ni = 0; ni < 4; ni++)
                    ldsm_x2_t(b[ni], Bb + kB + nboff[ni]);
#pragma unroll
                for (int mi = 0; mi < 2; mi++)
#pragma unroll
                    for (int ni = 0; ni < 4; ni++)
                        mma16816(acc[mi][ni], a[mi], b[ni]);
            }
        }
    };

    // ---- pipeline ----
    LOADA(0); LOADB(0);
    STORE(0, 0);
    __syncthreads();
#pragma unroll
    for (int kc = 0; kc < NCHUNK; kc++) {
        if (kc + 1 < NCHUNK) { LOADA(kc + 1); LOADB(kc + 1); }
        MMA(kc & 1);
        if (kc + 1 < NCHUNK) STORE((kc + 1) & 1, kc + 1);
        __syncthreads();
    }

    // ---- epilogue: bias add, store C, fused column stats ----
    float* s_s = (float*)smem;         // 128 floats
    float* s_q = (float*)smem + 128;   // 128 floats
    if (t < 128) { s_s[t] = 0.f; s_q[t] = 0.f; }
    __syncthreads();

    float* Cout = (MODE == 0) ? g_t1 : g_hc;
    int gidl = lane >> 2, tq = lane & 3;
    int colbase = wn * 32 + tq * 2;
    float2 bv[4];
#pragma unroll
    for (int ni = 0; ni < 4; ni++)
        bv[ni] = *(const float2*)&bias[c0 + colbase + ni * 8];

    float ssum[4][2] = {}, qsum[4][2] = {};
#pragma unroll
    for (int mi = 0; mi < 2; mi++) {
        int r0 = blockRow + wm * 32 + mi * 16 + gidl;
        int r1 = r0 + 8;
        bool ok0 = r0 < NN, ok1 = r1 < NN;
#pragma unroll
        for (int ni = 0; ni < 4; ni++) {
            float v0 = acc[mi][ni][0] + bv[ni].x;
            float v1 = acc[mi][ni][1] + bv[ni].y;
            float v2 = acc[mi][ni][2] + bv[ni].x;
            float v3 = acc[mi][ni][3] + bv[ni].y;
            int col = c0 + colbase + ni * 8;
            if (ok0) {
                *(float2*)&Cout[(size_t)r0 * NCOL + col] = make_float2(v0, v1);
                ssum[ni][0] += v0; qsum[ni][0] += v0 * v0;
                ssum[ni][1] += v1; qsum[ni][1] += v1 * v1;
            }
            if (ok1) {
                *(float2*)&Cout[(size_t)r1 * NCOL + col] = make_float2(v2, v3);
                ssum[ni][0] += v2; qsum[ni][0] += v2 * v2;
                ssum[ni][1] += v3; qsum[ni][1] += v3 * v3;
            }
        }
    }
#pragma unroll
    for (int ni = 0; ni < 4; ni++) {
        int cl = colbase + ni * 8;
        atomicAdd(&s_s[cl], ssum[ni][0]);
        atomicAdd(&s_s[cl + 1], ssum[ni][1]);
        atomicAdd(&s_q[cl], qsum[ni][0]);
        atomicAdd(&s_q[cl + 1], qsum[ni][1]);
    }
    __syncthreads();
    if (t < 128) {
        float* Sg = (MODE == 0) ? g_sum1 : g_sum2;
        float* Qg = (MODE == 0) ? g_sq1 : g_sq2;
        atomicAdd(&Sg[c0 + t], s_s[t]);
        atomicAdd(&Qg[c0 + t], s_q[t]);
    }
}

// ---------------- finalize BN affine: a = g/sqrt(var+eps), b = beta - mean*a ----------------
template <int WHICH>
__global__ void finalize_kernel(const float* __restrict__ gamma,
                                const float* __restrict__ beta) {
    constexpr int C = (WHICH == 0) ? 256 : 128;
    int c = threadIdx.x;
    if (c >= C) return;
    float s = (WHICH == 0) ? g_sum1[c] : g_sum2[c];
    float q = (WHICH == 0) ? g_sq1[c]  : g_sq2[c];
    float mean = s * (1.f / NN);
    float var  = q * (1.f / NN) - mean * mean;
    float inv  = rsqrtf(var + 1e-5f);
    float a = gamma[c] * inv;
    float b = beta[c] - mean * a;
    if (WHICH == 0) { g_a1[c] = a; g_c1[c] = b; }
    else            { g_a2[c] = a; g_c2[c] = b; }
}

// ---------------- apply final BN (+optional relu), write to g_h or d_out ----------------
__global__ void bnapply_kernel(float* __restrict__ dst, int do_relu) {
    int gid = blockIdx.x * blockDim.x + threadIdx.x;
    int node = gid >> 5;
    if (node >= NN) return;
    int c = (gid & 31) * 4;
    float4 v = *(const float4*)&g_hc[(size_t)node * 128 + c];
    float4 a = *(const float4*)&g_a2[c];
    float4 b = *(const float4*)&g_c2[c];
    float4 o;
    o.x = v.x * a.x + b.x; o.y = v.y * a.y + b.y;
    o.z = v.z * a.z + b.z; o.w = v.w * a.w + b.w;
    if (do_relu) {
        o.x = fmaxf(o.x, 0.f); o.y = fmaxf(o.y, 0.f);
        o.z = fmaxf(o.z, 0.f); o.w = fmaxf(o.w, 0.f);
    }
    float* d = dst ? dst : g_h;
    *(float4*)&d[(size_t)node * 128 + c] = o;
}

// ---------------- launch ----------------
extern "C" void kernel_launch(void* const* d_in, const int* in_sizes, int n_in,
                              void* d_out, int out_size) {
    const int*   x    = (const int*)d_in[0];
    const int*   z    = (const int*)d_in[1];
    const int*   ei   = (const int*)d_in[2];
    const int*   ea   = (const int*)d_in[3];
    const float* atom = (const float*)d_in[4];
    const float* zemb = (const float*)d_in[5];
    const float* bond = (const float*)d_in[6];
    const float* eps  = (const float*)d_in[7];
    const float* W1   = (const float*)d_in[8];
    const float* b1   = (const float*)d_in[9];
    const float* g1   = (const float*)d_in[10];
    const float* be1  = (const float*)d_in[11];
    const float* W2   = (const float*)d_in[12];
    const float* b2   = (const float*)d_in[13];
    const float* bng  = (const float*)d_in[14];
    const float* bnb  = (const float*)d_in[15];
    float* out = (float*)d_out;

    static bool attr_done = false;
    if (!attr_done) {
        cudaFuncSetAttribute(gemm_mma<0>, cudaFuncAttributeMaxDynamicSharedMemorySize, GEMM_SMEM);
        cudaFuncSetAttribute(gemm_mma<1>, cudaFuncAttributeMaxDynamicSharedMemorySize, GEMM_SMEM);
        attr_done = true;
    }

    const int NODE_BLKS = (NN * 32 + 255) / 256;
    const int EDGE_BLKS = (EE * 32 + 255) / 256;

    embed_kernel<<<NODE_BLKS, 256>>>(x, z, atom, zemb);
    for (int l = 0; l < 2; l++) {
        zero_kernel<<<NODE_BLKS, 256>>>();
        edge_kernel<<<EDGE_BLKS, 256>>>(ei, ea, bond + (size_t)l * 3 * 6 * 128);
        gemm_mma<0><<<dim3(NPAD / 128, 2), 512, GEMM_SMEM>>>(W1 + (size_t)l * 128 * 256,
                                                             b1 + l * 256, eps + l);
        finalize_kernel<0><<<1, 256>>>(g1 + l * 256, be1 + l * 256);
        gemm_mma<1><<<dim3(NPAD / 128, 1), 512, GEMM_SMEM>>>(W2 + (size_t)l * 256 * 128,
                                                             b2 + l * 128, eps + l);
        finalize_kernel<1><<<1, 128>>>(bng + l * 128, bnb + l * 128);
        bnapply_kernel<<<NODE_BLKS, 256>>>((l == 0) ? nullptr : out, (l == 0) ? 1 : 0);
    }
}

// round 7
// speedup vs baseline: 1.2262x; 1.1001x over previous
#include <cuda_runtime.h>
#include <cuda_bf16.h>
#include <cstddef>
#include <cstdint>

#define NN   100000
#define NPAD 100096   // 1564 * 64
#define EE   1600000

// ---------------- scratch (device globals; no allocation allowed) ----------------
__device__ __align__(16) float g_h  [(size_t)NPAD * 128];
__device__ __align__(16) float g_pre[(size_t)NPAD * 128];   // (1+eps)h + agg
__device__ __align__(16) float g_t1 [(size_t)NPAD * 256];
__device__ __align__(16) float g_hc [(size_t)NPAD * 128];
__device__ __align__(16) float g_sum1[256];
__device__ __align__(16) float g_sq1 [256];
__device__ __align__(16) float g_sum2[128];
__device__ __align__(16) float g_sq2 [128];
__device__ __align__(16) float g_a1[256];
__device__ __align__(16) float g_c1[256];
__device__ __align__(16) float g_a2[128];
__device__ __align__(16) float g_c2[128];
// CSR build
__device__ int g_deg[NN];
__device__ int g_cur[NN];
__device__ int g_off[NN + 1];
__device__ int g_bsum[512];
__device__ int g_es[EE];          // packed: src | a0<<20 | a1<<23 | a2<<26

// ---------------- helpers ----------------
__device__ __forceinline__ uint32_t smem_u32(const void* p) {
    uint32_t a;
    asm("{ .reg .u64 t; cvta.to.shared.u64 t, %1; cvt.u32.u64 %0, t; }" : "=r"(a) : "l"(p));
    return a;
}

__device__ __forceinline__ void ldsm_x4(uint32_t (&r)[4], uint32_t addr) {
    asm volatile("ldmatrix.sync.aligned.m8n8.x4.shared.b16 {%0,%1,%2,%3}, [%4];"
                 : "=r"(r[0]), "=r"(r[1]), "=r"(r[2]), "=r"(r[3]) : "r"(addr));
}

__device__ __forceinline__ void ldsm_x2_t(uint32_t (&r)[2], uint32_t addr) {
    asm volatile("ldmatrix.sync.aligned.m8n8.x2.trans.shared.b16 {%0,%1}, [%2];"
                 : "=r"(r[0]), "=r"(r[1]) : "r"(addr));
}

__device__ __forceinline__ void mma16816(float (&d)[4], const uint32_t (&a)[4],
                                         const uint32_t (&b)[2]) {
    asm volatile("mma.sync.aligned.m16n8k16.row.col.f32.bf16.bf16.f32 "
                 "{%0,%1,%2,%3}, {%4,%5,%6,%7}, {%8,%9}, {%0,%1,%2,%3};"
                 : "+f"(d[0]), "+f"(d[1]), "+f"(d[2]), "+f"(d[3])
                 : "r"(a[0]), "r"(a[1]), "r"(a[2]), "r"(a[3]), "r"(b[0]), "r"(b[1]));
}

__device__ __forceinline__ uint32_t sw128(uint32_t off) {
    return off ^ ((off >> 3) & 0x70);
}

// split fp32 pair -> packed bf16x2 hi + bf16x2 lo
__device__ __forceinline__ void split2(float x, float y, uint32_t& hi, uint32_t& lo) {
    __nv_bfloat162 h = __floats2bfloat162_rn(x, y);
    float hx = __low2float(h), hy = __high2float(h);
    __nv_bfloat162 l = __floats2bfloat162_rn(x - hx, y - hy);
    hi = *reinterpret_cast<uint32_t*>(&h);
    lo = *reinterpret_cast<uint32_t*>(&l);
}

// ---------------- h0 = sum_f atom_emb[f][x[:,f]] + z_emb[z] ----------------
__global__ void embed_kernel(const int* __restrict__ x, const int* __restrict__ z,
                             const float* __restrict__ atom, const float* __restrict__ zemb) {
    int gid = blockIdx.x * blockDim.x + threadIdx.x;
    int node = gid >> 5;
    if (node >= NN) return;
    int c = (gid & 31) * 4;
    const int* xr = x + node * 9;
    float4 acc = *(const float4*)&zemb[(size_t)z[node] * 128 + c];
#pragma unroll
    for (int f = 0; f < 9; f++) {
        int idx = xr[f];
        float4 v = *(const float4*)&atom[((size_t)(f * 119 + idx)) * 128 + c];
        acc.x += v.x; acc.y += v.y; acc.z += v.z; acc.w += v.w;
    }
    *(float4*)&g_h[(size_t)node * 128 + c] = acc;
}

// ---------------- CSR build (once per launch; edge_index is layer-invariant) ------
__global__ void zero_build_kernel() {
    int i = blockIdx.x * blockDim.x + threadIdx.x;
    if (i < NN) { g_deg[i] = 0; g_cur[i] = 0; }
}

__global__ void hist_kernel(const int* __restrict__ ei) {
    int e = blockIdx.x * blockDim.x + threadIdx.x;
    if (e < EE) atomicAdd(&g_deg[ei[EE + e]], 1);
}

__global__ void scan1_kernel() {   // per-block sums of g_deg
    __shared__ int s[256];
    int i = blockIdx.x * 256 + threadIdx.x;
    s[threadIdx.x] = (i < NN) ? g_deg[i] : 0;
    __syncthreads();
    for (int o = 128; o > 0; o >>= 1) {
        if (threadIdx.x < o) s[threadIdx.x] += s[threadIdx.x + o];
        __syncthreads();
    }
    if (threadIdx.x == 0) g_bsum[blockIdx.x] = s[0];
}

__global__ void scan2_kernel(int nb) {   // serial exclusive scan of block sums
    if (threadIdx.x == 0 && blockIdx.x == 0) {
        int s = 0;
        for (int i = 0; i < nb; i++) { int t = g_bsum[i]; g_bsum[i] = s; s += t; }
        g_off[NN] = s;
    }
}

__global__ void scan3_kernel() {   // per-block exclusive scan -> g_off
    __shared__ int s[256];
    int i = blockIdx.x * 256 + threadIdx.x;
    int v = (i < NN) ? g_deg[i] : 0;
    s[threadIdx.x] = v;
    __syncthreads();
    // Hillis-Steele inclusive
    for (int o = 1; o < 256; o <<= 1) {
        int t = (threadIdx.x >= o) ? s[threadIdx.x - o] : 0;
        __syncthreads();
        s[threadIdx.x] += t;
        __syncthreads();
    }
    if (i < NN) g_off[i] = g_bsum[blockIdx.x] + s[threadIdx.x] - v;
}

__global__ void scatter_kernel(const int* __restrict__ ei, const int* __restrict__ ea) {
    int e = blockIdx.x * blockDim.x + threadIdx.x;
    if (e >= EE) return;
    int dst = ei[EE + e];
    int pos = g_off[dst] + atomicAdd(&g_cur[dst], 1);
    int src = ei[e];
    int a0 = ea[e * 3 + 0] & 7, a1 = ea[e * 3 + 1] & 7, a2 = ea[e * 3 + 2] & 7;
    g_es[pos] = src | (a0 << 20) | (a1 << 23) | (a2 << 26);
}

// ---------------- aggregate (gather): pre[d] = (1+eps)h[d] + sum relu(h[src]+bond) --
__global__ void agg_kernel(const float* __restrict__ bt, const float* __restrict__ epsp) {
    __shared__ float s_bond[18 * 128];   // 9KB: 3 tables x 6 rows x 128
    for (int i = threadIdx.x; i < 18 * 128; i += 256) s_bond[i] = bt[i];
    __syncthreads();

    int w = (blockIdx.x * 256 + threadIdx.x) >> 5;   // dst node (grid covers NN exactly)
    int lane = threadIdx.x & 31;
    int c = lane * 4;
    int beg = g_off[w], end = g_off[w + 1];
    float epsv = 1.f + epsp[0];

    float4 hv = *(const float4*)&g_h[(size_t)w * 128 + c];
    float4 acc = make_float4(epsv * hv.x, epsv * hv.y, epsv * hv.z, epsv * hv.w);

    for (int p = beg; p < end; p++) {
        int pk = g_es[p];
        int src = pk & 0xFFFFF;
        float4 h4 = *(const float4*)&g_h[(size_t)src * 128 + c];
        const float4 b0 = *(const float4*)&s_bond[(((pk >> 20) & 7)) * 128 + c];
        const float4 b1 = *(const float4*)&s_bond[(6 + ((pk >> 23) & 7)) * 128 + c];
        const float4 b2 = *(const float4*)&s_bond[(12 + ((pk >> 26) & 7)) * 128 + c];
        acc.x += fmaxf(h4.x + b0.x + b1.x + b2.x, 0.f);
        acc.y += fmaxf(h4.y + b0.y + b1.y + b2.y, 0.f);
        acc.z += fmaxf(h4.z + b0.z + b1.z + b2.z, 0.f);
        acc.w += fmaxf(h4.w + b0.w + b1.w + b2.w, 0.f);
    }
    *(float4*)&g_pre[(size_t)w * 128 + c] = acc;
}

// ---------------- zero BN stat accumulators ----------------
__global__ void zero_stats_kernel() {
    int t = threadIdx.x;
    if (t < 256) { g_sum1[t] = 0.f; g_sq1[t] = 0.f; }
    if (t < 128) { g_sum2[t] = 0.f; g_sq2[t] = 0.f; }
}

// ---------------- mma.sync bf16-split GEMM, 64x128 tile, 2 CTAs/SM ----------------
// 256 threads, 8 warps (2 row x 4 col), warp tile 32x32, K chunked by 64,
// double-buffered smem stages (48KB each), register prefetch for A.
// 3 split terms: Ahi*Bhi + Ahi*Blo + Alo*Bhi.
// MODE 0: A = g_pre [N,128];           C = A@W1 + b1 -> g_t1 [N,256] (grid.y=2)
// MODE 1: A = relu(g_t1*a1+c1) [N,256]; C = A@W2 + b2 -> g_hc [N,128] (grid.y=1)
// Epilogue: bias, store, fused BN column sums/sumsq (rows < NN).

#define STAGE_BYTES 49152                     // A hi 8K + A lo 8K + B hi 16K + B lo 16K
#define GEMM_SMEM   (2 * STAGE_BYTES + 2048)

template <int MODE>
__global__ __launch_bounds__(256, 2) void gemm_mma(const float* __restrict__ W,
                                                   const float* __restrict__ bias,
                                                   const float* __restrict__ epsp) {
    constexpr int KTOT   = (MODE == 0) ? 128 : 256;
    constexpr int NCHUNK = KTOT / 64;
    constexpr int NCOL   = (MODE == 0) ? 256 : 128;

    extern __shared__ char smem[];
    uint32_t sbase = smem_u32(smem);
    float* s_a1 = (float*)(smem + 2 * STAGE_BYTES);
    float* s_c1 = (float*)(smem + 2 * STAGE_BYTES + 1024);

    int t = threadIdx.x;
    int lane = t & 31;
    int wid = t >> 5;
    int wm = wid & 1;        // 0..1 -> 32-row block
    int wn = wid >> 1;       // 0..3 -> 32-col block
    int blockRow = blockIdx.x * 64;
    int c0 = blockIdx.y * 128;

    if constexpr (MODE == 1) {
        if (t < 256) { s_a1[t] = g_a1[t]; s_c1[t] = g_c1[t]; }
        __syncthreads();
    }

    // staging maps (256 threads; A: 64x64, B: 64x128 per chunk)
    int arow = t >> 2;             // 0..63
    int ac0  = (t & 3) * 16;       // 0,16,32,48
    int bkr  = t >> 2;             // 0..63
    int bn0  = (t & 3) * 32;       // 0,32,64,96

    // mma lane addressing
    int a_r  = wm * 32 + (lane & 15);
    int a_kh = (lane >> 4) * 8;
    uint32_t swa = (uint32_t)((a_r & 7) << 4);
    int bl   = lane & 15;
    int b_k7 = bl & 7;
    int b_kh = ((bl >> 3) & 1) * 8;
    uint32_t nboff[4];
#pragma unroll
    for (int ni = 0; ni < 4; ni++)
        nboff[ni] = ((uint32_t)((wn * 32 + ni * 8) * 2)) ^ ((uint32_t)(b_k7 << 4));

    float acc[2][4][4];
#pragma unroll
    for (int mi = 0; mi < 2; mi++)
#pragma unroll
        for (int ni = 0; ni < 4; ni++)
#pragma unroll
            for (int j = 0; j < 4; j++) acc[mi][ni][j] = 0.f;

    float4 hA[4];   // A prefetch

    auto LOADA = [&](int kc) {
        size_t r = (size_t)(blockRow + arow);
        int kg = kc * 64 + ac0;
#pragma unroll
        for (int q = 0; q < 4; q++) {
            if constexpr (MODE == 0)
                hA[q] = *(const float4*)&g_pre[r * 128 + kg + q * 4];
            else
                hA[q] = *(const float4*)&g_t1[r * 256 + kg + q * 4];
        }
    };
    auto STORE = [&](int s, int kc) {
        char* Ah = smem + s * STAGE_BYTES;
        char* Al = Ah + 8192;
        char* Bh = Ah + 16384;
        char* Bl = Ah + 32768;
#pragma unroll
        for (int q = 0; q < 4; q++) {
            int cl = ac0 + q * 4;
            float4 a = hA[q];
            if constexpr (MODE == 1) {
                int kg = kc * 64 + cl;
                float4 sc = *(const float4*)&s_a1[kg];
                float4 sh = *(const float4*)&s_c1[kg];
                a.x = fmaxf(fmaf(a.x, sc.x, sh.x), 0.f);
                a.y = fmaxf(fmaf(a.y, sc.y, sh.y), 0.f);
                a.z = fmaxf(fmaf(a.z, sc.z, sh.z), 0.f);
                a.w = fmaxf(fmaf(a.w, sc.w, sh.w), 0.f);
            }
            uint32_t h01, l01, h23, l23;
            split2(a.x, a.y, h01, l01);
            split2(a.z, a.w, h23, l23);
            uint32_t off = sw128((uint32_t)(arow * 128 + cl * 2));
            *(uint2*)(Ah + off) = make_uint2(h01, h23);
            *(uint2*)(Al + off) = make_uint2(l01, l23);
        }
        // B: load from W (L2-hot) + split + store, 8 float4 per thread
#pragma unroll
        for (int q = 0; q < 8; q++) {
            int n = bn0 + q * 4;
            float4 w = *(const float4*)&W[(size_t)(kc * 64 + bkr) * NCOL + c0 + n];
            uint32_t h01, l01, h23, l23;
            split2(w.x, w.y, h01, l01);
            split2(w.z, w.w, h23, l23);
            uint32_t off = (uint32_t)(bkr * 256) +
                           (((uint32_t)(n * 2)) ^ ((uint32_t)((bkr & 7) << 4)));
            *(uint2*)(Bh + off) = make_uint2(h01, h23);
            *(uint2*)(Bl + off) = make_uint2(l01, l23);
        }
    };
    auto MMA = [&](int s) {
        uint32_t Au   = sbase + s * STAGE_BYTES;
        uint32_t Alou = Au + 8192;
        uint32_t Bu   = Au + 16384;
        uint32_t Blou = Au + 32768;
#pragma unroll
        for (int term = 0; term < 3; term++) {
            uint32_t Ab = (term == 2) ? Alou : Au;
            uint32_t Bb = (term == 1) ? Blou : Bu;
#pragma unroll
            for (int kk = 0; kk < 4; kk++) {
                int k0 = kk * 16;
                uint32_t a[2][4];
                uint32_t b[4][2];
                uint32_t kA = (((uint32_t)((k0 + a_kh) * 2)) ^ swa);
#pragma unroll
                for (int mi = 0; mi < 2; mi++)
                    ldsm_x4(a[mi], Ab + (uint32_t)((a_r + mi * 16) * 128) + kA);
                uint32_t kB = (uint32_t)((k0 + b_kh + b_k7) * 256);
#pragma unroll
                for (int ni = 0; ni < 4; ni++)
                    ldsm_x2_t(b[ni], Bb + kB + nboff[ni]);
#pragma unroll
                for (int mi = 0; mi < 2; mi++)
#pragma unroll
                    for (int ni = 0; ni < 4; ni++)
                        mma16816(acc[mi][ni], a[mi], b[ni]);
            }
        }
    };

    // ---- pipeline ----
    LOADA(0);
    STORE(0, 0);
    __syncthreads();
#pragma unroll
    for (int kc = 0; kc < NCHUNK; kc++) {
        if (kc + 1 < NCHUNK) LOADA(kc + 1);
        MMA(kc & 1);
        if (kc + 1 < NCHUNK) STORE((kc + 1) & 1, kc + 1);
        __syncthreads();
    }

    // ---- epilogue: bias add, store C, fused column stats ----
    float* s_s = (float*)smem;         // 128 floats (stage 0 free after last MMA)
    float* s_q = (float*)smem + 128;
    if (t < 128) { s_s[t] = 0.f; s_q[t] = 0.f; }
    __syncthreads();

    float* Cout = (MODE == 0) ? g_t1 : g_hc;
    int gidl = lane >> 2, tq = lane & 3;
    int colbase = wn * 32 + tq * 2;
    float2 bv[4];
#pragma unroll
    for (int ni = 0; ni < 4; ni++)
        bv[ni] = *(const float2*)&bias[c0 + colbase + ni * 8];

    float ssum[4][2] = {}, qsum[4][2] = {};
#pragma unroll
    for (int mi = 0; mi < 2; mi++) {
        int r0 = blockRow + wm * 32 + mi * 16 + gidl;
        int r1 = r0 + 8;
        bool ok0 = r0 < NN, ok1 = r1 < NN;
#pragma unroll
        for (int ni = 0; ni < 4; ni++) {
            float v0 = acc[mi][ni][0] + bv[ni].x;
            float v1 = acc[mi][ni][1] + bv[ni].y;
            float v2 = acc[mi][ni][2] + bv[ni].x;
            float v3 = acc[mi][ni][3] + bv[ni].y;
            int col = c0 + colbase + ni * 8;
            if (ok0) {
                *(float2*)&Cout[(size_t)r0 * NCOL + col] = make_float2(v0, v1);
                ssum[ni][0] += v0; qsum[ni][0] += v0 * v0;
                ssum[ni][1] += v1; qsum[ni][1] += v1 * v1;
            }
            if (ok1) {
                *(float2*)&Cout[(size_t)r1 * NCOL + col] = make_float2(v2, v3);
                ssum[ni][0] += v2; qsum[ni][0] += v2 * v2;
                ssum[ni][1] += v3; qsum[ni][1] += v3 * v3;
            }
        }
    }
#pragma unroll
    for (int ni = 0; ni < 4; ni++) {
        int cl = colbase + ni * 8;
        atomicAdd(&s_s[cl], ssum[ni][0]);
        atomicAdd(&s_s[cl + 1], ssum[ni][1]);
        atomicAdd(&s_q[cl], qsum[ni][0]);
        atomicAdd(&s_q[cl + 1], qsum[ni][1]);
    }
    __syncthreads();
    if (t < 128) {
        float* Sg = (MODE == 0) ? g_sum1 : g_sum2;
        float* Qg = (MODE == 0) ? g_sq1 : g_sq2;
        atomicAdd(&Sg[c0 + t], s_s[t]);
        atomicAdd(&Qg[c0 + t], s_q[t]);
    }
}

// ---------------- finalize BN affine: a = g/sqrt(var+eps), b = beta - mean*a --------
template <int WHICH>
__global__ void finalize_kernel(const float* __restrict__ gamma,
                                const float* __restrict__ beta) {
    constexpr int C = (WHICH == 0) ? 256 : 128;
    int c = threadIdx.x;
    if (c >= C) return;
    float s = (WHICH == 0) ? g_sum1[c] : g_sum2[c];
    float q = (WHICH == 0) ? g_sq1[c]  : g_sq2[c];
    float mean = s * (1.f / NN);
    float var  = q * (1.f / NN) - mean * mean;
    float inv  = rsqrtf(var + 1e-5f);
    float a = gamma[c] * inv;
    float b = beta[c] - mean * a;
    if (WHICH == 0) { g_a1[c] = a; g_c1[c] = b; }
    else            { g_a2[c] = a; g_c2[c] = b; }
}

// ---------------- apply final BN (+optional relu), write to g_h or d_out -----------
__global__ void bnapply_kernel(float* __restrict__ dst, int do_relu) {
    int gid = blockIdx.x * blockDim.x + threadIdx.x;
    int node = gid >> 5;
    if (node >= NN) return;
    int c = (gid & 31) * 4;
    float4 v = *(const float4*)&g_hc[(size_t)node * 128 + c];
    float4 a = *(const float4*)&g_a2[c];
    float4 b = *(const float4*)&g_c2[c];
    float4 o;
    o.x = v.x * a.x + b.x; o.y = v.y * a.y + b.y;
    o.z = v.z * a.z + b.z; o.w = v.w * a.w + b.w;
    if (do_relu) {
        o.x = fmaxf(o.x, 0.f); o.y = fmaxf(o.y, 0.f);
        o.z = fmaxf(o.z, 0.f); o.w = fmaxf(o.w, 0.f);
    }
    float* d = dst ? dst : g_h;
    *(float4*)&d[(size_t)node * 128 + c] = o;
}

// ---------------- launch ----------------
extern "C" void kernel_launch(void* const* d_in, const int* in_sizes, int n_in,
                              void* d_out, int out_size) {
    const int*   x    = (const int*)d_in[0];
    const int*   z    = (const int*)d_in[1];
    const int*   ei   = (const int*)d_in[2];
    const int*   ea   = (const int*)d_in[3];
    const float* atom = (const float*)d_in[4];
    const float* zemb = (const float*)d_in[5];
    const float* bond = (const float*)d_in[6];
    const float* eps  = (const float*)d_in[7];
    const float* W1   = (const float*)d_in[8];
    const float* b1   = (const float*)d_in[9];
    const float* g1   = (const float*)d_in[10];
    const float* be1  = (const float*)d_in[11];
    const float* W2   = (const float*)d_in[12];
    const float* b2   = (const float*)d_in[13];
    const float* bng  = (const float*)d_in[14];
    const float* bnb  = (const float*)d_in[15];
    float* out = (float*)d_out;

    static bool attr_done = false;
    if (!attr_done) {
        cudaFuncSetAttribute(gemm_mma<0>, cudaFuncAttributeMaxDynamicSharedMemorySize, GEMM_SMEM);
        cudaFuncSetAttribute(gemm_mma<1>, cudaFuncAttributeMaxDynamicSharedMemorySize, GEMM_SMEM);
        attr_done = true;
    }

    const int NODE_BLKS = (NN * 32 + 255) / 256;   // 12500
    const int EDGE_BLKS = (EE + 255) / 256;        // 6250
    const int NB        = (NN + 255) / 256;        // 391

    embed_kernel<<<NODE_BLKS, 256>>>(x, z, atom, zemb);

    // CSR build (edge_index is the same for both layers)
    zero_build_kernel<<<NB, 256>>>();
    hist_kernel<<<EDGE_BLKS, 256>>>(ei);
    scan1_kernel<<<NB, 256>>>();
    scan2_kernel<<<1, 32>>>(NB);
    scan3_kernel<<<NB, 256>>>();
    scatter_kernel<<<EDGE_BLKS, 256>>>(ei, ea);

    for (int l = 0; l < 2; l++) {
        zero_stats_kernel<<<1, 256>>>();
        agg_kernel<<<NODE_BLKS, 256>>>(bond + (size_t)l * 3 * 6 * 128, eps + l);
        gemm_mma<0><<<dim3(NPAD / 64, 2), 256, GEMM_SMEM>>>(W1 + (size_t)l * 128 * 256,
                                                            b1 + l * 256, eps + l);
        finalize_kernel<0><<<1, 256>>>(g1 + l * 256, be1 + l * 256);
        gemm_mma<1><<<dim3(NPAD / 64, 1), 256, GEMM_SMEM>>>(W2 + (size_t)l * 256 * 128,
                                                            b2 + l * 128, eps + l);
        finalize_kernel<1><<<1, 128>>>(bng + l * 128, bnb + l * 128);
        bnapply_kernel<<<NODE_BLKS, 256>>>((l == 0) ? nullptr : out, (l == 0) ? 1 : 0);
    }
}

// round 8
// speedup vs baseline: 1.3834x; 1.1282x over previous
#include <cuda_runtime.h>
#include <cuda_bf16.h>
#include <cstddef>
#include <cstdint>

#define NN   100000
#define NPAD 100096   // 1564 * 64
#define EE   1600000

// ---------------- scratch (device globals; no allocation allowed) ----------------
__device__ __align__(16) float g_h  [(size_t)NPAD * 128];
__device__ __align__(16) float g_pre[(size_t)NPAD * 128];   // (1+eps)h + agg
__device__ __align__(16) float g_t1 [(size_t)NPAD * 256];
__device__ __align__(16) float g_hc [(size_t)NPAD * 128];
__device__ __align__(16) float g_sum1[256];
__device__ __align__(16) float g_sq1 [256];
__device__ __align__(16) float g_sum2[128];
__device__ __align__(16) float g_sq2 [128];
__device__ __align__(16) float g_a1[256];
__device__ __align__(16) float g_c1[256];
__device__ __align__(16) float g_a2[128];
__device__ __align__(16) float g_c2[128];
// pre-split weights (bf16 hi/lo), layer-major
__device__ __align__(16) __nv_bfloat16 g_W1h[2 * 32768];
__device__ __align__(16) __nv_bfloat16 g_W1l[2 * 32768];
__device__ __align__(16) __nv_bfloat16 g_W2h[2 * 32768];
__device__ __align__(16) __nv_bfloat16 g_W2l[2 * 32768];
// CSR build
__device__ int g_deg[NN];
__device__ int g_cur[NN];
__device__ int g_off[NN + 1];
__device__ int g_bsum[512];
__device__ int g_es[EE];          // packed: src | a0<<20 | a1<<23 | a2<<26

// ---------------- helpers ----------------
__device__ __forceinline__ uint32_t smem_u32(const void* p) {
    uint32_t a;
    asm("{ .reg .u64 t; cvta.to.shared.u64 t, %1; cvt.u32.u64 %0, t; }" : "=r"(a) : "l"(p));
    return a;
}

__device__ __forceinline__ void ldsm_x4(uint32_t (&r)[4], uint32_t addr) {
    asm volatile("ldmatrix.sync.aligned.m8n8.x4.shared.b16 {%0,%1,%2,%3}, [%4];"
                 : "=r"(r[0]), "=r"(r[1]), "=r"(r[2]), "=r"(r[3]) : "r"(addr));
}

__device__ __forceinline__ void ldsm_x2_t(uint32_t (&r)[2], uint32_t addr) {
    asm volatile("ldmatrix.sync.aligned.m8n8.x2.trans.shared.b16 {%0,%1}, [%2];"
                 : "=r"(r[0]), "=r"(r[1]) : "r"(addr));
}

__device__ __forceinline__ void mma16816(float (&d)[4], const uint32_t (&a)[4],
                                         const uint32_t (&b)[2]) {
    asm volatile("mma.sync.aligned.m16n8k16.row.col.f32.bf16.bf16.f32 "
                 "{%0,%1,%2,%3}, {%4,%5,%6,%7}, {%8,%9}, {%0,%1,%2,%3};"
                 : "+f"(d[0]), "+f"(d[1]), "+f"(d[2]), "+f"(d[3])
                 : "r"(a[0]), "r"(a[1]), "r"(a[2]), "r"(a[3]), "r"(b[0]), "r"(b[1]));
}

__device__ __forceinline__ uint32_t sw128(uint32_t off) {
    return off ^ ((off >> 3) & 0x70);
}

// split fp32 pair -> packed bf16x2 hi + bf16x2 lo
__device__ __forceinline__ void split2(float x, float y, uint32_t& hi, uint32_t& lo) {
    __nv_bfloat162 h = __floats2bfloat162_rn(x, y);
    float hx = __low2float(h), hy = __high2float(h);
    __nv_bfloat162 l = __floats2bfloat162_rn(x - hx, y - hy);
    hi = *reinterpret_cast<uint32_t*>(&h);
    lo = *reinterpret_cast<uint32_t*>(&l);
}

// ---------------- h0 = sum_f atom_emb[f][x[:,f]] + z_emb[z]  (+ zero deg/cur) -------
__global__ void embed_kernel(const int* __restrict__ x, const int* __restrict__ z,
                             const float* __restrict__ atom, const float* __restrict__ zemb) {
    int gid = blockIdx.x * blockDim.x + threadIdx.x;
    int node = gid >> 5;
    if (node >= NN) return;
    int lane = gid & 31;
    if (lane == 0) { g_deg[node] = 0; g_cur[node] = 0; }
    int c = lane * 4;
    const int* xr = x + node * 9;
    float4 acc = *(const float4*)&zemb[(size_t)z[node] * 128 + c];
#pragma unroll
    for (int f = 0; f < 9; f++) {
        int idx = xr[f];
        float4 v = *(const float4*)&atom[((size_t)(f * 119 + idx)) * 128 + c];
        acc.x += v.x; acc.y += v.y; acc.z += v.z; acc.w += v.w;
    }
    *(float4*)&g_h[(size_t)node * 128 + c] = acc;
}

// ---------------- pre-split weights into bf16 hi/lo ----------------
__global__ void prep_w(const float* __restrict__ W1, const float* __restrict__ W2) {
    int i = blockIdx.x * blockDim.x + threadIdx.x;
    if (i >= 2 * 32768) return;
    float w = W1[i];
    __nv_bfloat16 h = __float2bfloat16_rn(w);
    g_W1h[i] = h; g_W1l[i] = __float2bfloat16_rn(w - __bfloat162float(h));
    w = W2[i];
    h = __float2bfloat16_rn(w);
    g_W2h[i] = h; g_W2l[i] = __float2bfloat16_rn(w - __bfloat162float(h));
}

// ---------------- CSR build (once per launch; edge_index is layer-invariant) ------
__global__ void hist_kernel(const int* __restrict__ ei) {
    int e = blockIdx.x * blockDim.x + threadIdx.x;
    if (e < EE) atomicAdd(&g_deg[ei[EE + e]], 1);
}

__global__ void scan1_kernel() {   // per-block sums of g_deg
    __shared__ int s[256];
    int i = blockIdx.x * 256 + threadIdx.x;
    s[threadIdx.x] = (i < NN) ? g_deg[i] : 0;
    __syncthreads();
    for (int o = 128; o > 0; o >>= 1) {
        if (threadIdx.x < o) s[threadIdx.x] += s[threadIdx.x + o];
        __syncthreads();
    }
    if (threadIdx.x == 0) g_bsum[blockIdx.x] = s[0];
}

__global__ void scan2_kernel(int nb) {   // serial exclusive scan of block sums
    if (threadIdx.x == 0 && blockIdx.x == 0) {
        int s = 0;
        for (int i = 0; i < nb; i++) { int t = g_bsum[i]; g_bsum[i] = s; s += t; }
        g_off[NN] = s;
    }
}

__global__ void scan3_kernel() {   // per-block exclusive scan -> g_off
    __shared__ int s[256];
    int i = blockIdx.x * 256 + threadIdx.x;
    int v = (i < NN) ? g_deg[i] : 0;
    s[threadIdx.x] = v;
    __syncthreads();
    for (int o = 1; o < 256; o <<= 1) {
        int t = (threadIdx.x >= o) ? s[threadIdx.x - o] : 0;
        __syncthreads();
        s[threadIdx.x] += t;
        __syncthreads();
    }
    if (i < NN) g_off[i] = g_bsum[blockIdx.x] + s[threadIdx.x] - v;
}

__global__ void scatter_kernel(const int* __restrict__ ei, const int* __restrict__ ea) {
    int e = blockIdx.x * blockDim.x + threadIdx.x;
    if (e >= EE) return;
    int dst = ei[EE + e];
    int pos = g_off[dst] + atomicAdd(&g_cur[dst], 1);
    int src = ei[e];
    int a0 = ea[e * 3 + 0] & 7, a1 = ea[e * 3 + 1] & 7, a2 = ea[e * 3 + 2] & 7;
    g_es[pos] = src | (a0 << 20) | (a1 << 23) | (a2 << 26);
}

// ---------------- aggregate (gather) --------------------------------------------
// BNF=0: h = g_h[.]                       (layer 0)
// BNF=1: h = relu(g_hc[.]*a2 + c2)        (layer 1; folds previous bnapply)
// pre[d] = (1+eps)*h[d] + sum_edges relu(h[src] + bond)
// Block 0 additionally zeroes the BN stat accumulators for this layer.
template <int BNF>
__global__ void agg_kernel(const float* __restrict__ bt, const float* __restrict__ epsp) {
    __shared__ float s_bond[18 * 128];   // 9KB: 3 tables x 6 rows x 128
    for (int i = threadIdx.x; i < 18 * 128; i += 256) s_bond[i] = bt[i];
    if (blockIdx.x == 0) {
        int t = threadIdx.x;
        if (t < 256) { g_sum1[t] = 0.f; g_sq1[t] = 0.f; }
        if (t < 128) { g_sum2[t] = 0.f; g_sq2[t] = 0.f; }
    }
    __syncthreads();

    int w = (blockIdx.x * 256 + threadIdx.x) >> 5;
    int lane = threadIdx.x & 31;
    int c = lane * 4;
    int beg = g_off[w], end = g_off[w + 1];
    float epsv = 1.f + epsp[0];

    float4 av, cv;
    if constexpr (BNF == 1) {
        av = *(const float4*)&g_a2[c];
        cv = *(const float4*)&g_c2[c];
    }

    auto LDH = [&](int src) -> float4 {
        if constexpr (BNF == 0) {
            return *(const float4*)&g_h[(size_t)src * 128 + c];
        } else {
            float4 v = *(const float4*)&g_hc[(size_t)src * 128 + c];
            float4 o;
            o.x = fmaxf(fmaf(v.x, av.x, cv.x), 0.f);
            o.y = fmaxf(fmaf(v.y, av.y, cv.y), 0.f);
            o.z = fmaxf(fmaf(v.z, av.z, cv.z), 0.f);
            o.w = fmaxf(fmaf(v.w, av.w, cv.w), 0.f);
            return o;
        }
    };

    float4 hv = LDH(w);
    float4 acc = make_float4(epsv * hv.x, epsv * hv.y, epsv * hv.z, epsv * hv.w);

    auto ACCUM = [&](const float4& h4, int pk) {
        const float4 b0 = *(const float4*)&s_bond[(((pk >> 20) & 7)) * 128 + c];
        const float4 b1 = *(const float4*)&s_bond[(6 + ((pk >> 23) & 7)) * 128 + c];
        const float4 b2 = *(const float4*)&s_bond[(12 + ((pk >> 26) & 7)) * 128 + c];
        acc.x += fmaxf(h4.x + b0.x + b1.x + b2.x, 0.f);
        acc.y += fmaxf(h4.y + b0.y + b1.y + b2.y, 0.f);
        acc.z += fmaxf(h4.z + b0.z + b1.z + b2.z, 0.f);
        acc.w += fmaxf(h4.w + b0.w + b1.w + b2.w, 0.f);
    };

    int p = beg;
    for (; p + 4 <= end; p += 4) {
        int pk0 = g_es[p + 0], pk1 = g_es[p + 1];
        int pk2 = g_es[p + 2], pk3 = g_es[p + 3];
        float4 h0 = LDH(pk0 & 0xFFFFF);
        float4 h1 = LDH(pk1 & 0xFFFFF);
        float4 h2 = LDH(pk2 & 0xFFFFF);
        float4 h3 = LDH(pk3 & 0xFFFFF);
        ACCUM(h0, pk0); ACCUM(h1, pk1); ACCUM(h2, pk2); ACCUM(h3, pk3);
    }
    for (; p < end; p++) {
        int pk = g_es[p];
        float4 h4 = LDH(pk & 0xFFFFF);
        ACCUM(h4, pk);
    }
    *(float4*)&g_pre[(size_t)w * 128 + c] = acc;
}

// ---------------- mma.sync bf16-split GEMM, 64x128 tile, 2 CTAs/SM ----------------
// 256 threads, 8 warps (2 row x 4 col), warp tile 32x32, K chunked by 64,
// double-buffered smem stages (48KB each), register prefetch for A.
// B read from pre-split bf16 hi/lo globals (prep_w).
// MODE 0: A = g_pre [N,128];            C = A@W1 + b1 -> g_t1 [N,256] (grid.y=2)
// MODE 1: A = relu(g_t1*a1+c1) [N,256]; C = A@W2 + b2 -> g_hc [N,128] (grid.y=1)
// Epilogue: bias, store, fused BN column sums/sumsq (rows < NN).

#define STAGE_BYTES 49152                     // A hi 8K + A lo 8K + B hi 16K + B lo 16K
#define GEMM_SMEM   (2 * STAGE_BYTES + 2048)

template <int MODE>
__global__ __launch_bounds__(256, 2) void gemm_mma(const float* __restrict__ bias,
                                                   int layer) {
    constexpr int KTOT   = (MODE == 0) ? 128 : 256;
    constexpr int NCHUNK = KTOT / 64;
    constexpr int NCOL   = (MODE == 0) ? 256 : 128;

    extern __shared__ char smem[];
    uint32_t sbase = smem_u32(smem);
    float* s_a1 = (float*)(smem + 2 * STAGE_BYTES);
    float* s_c1 = (float*)(smem + 2 * STAGE_BYTES + 1024);

    const __nv_bfloat16* Wh = (MODE == 0) ? (g_W1h + layer * 32768) : (g_W2h + layer * 32768);
    const __nv_bfloat16* Wl = (MODE == 0) ? (g_W1l + layer * 32768) : (g_W2l + layer * 32768);

    int t = threadIdx.x;
    int lane = t & 31;
    int wid = t >> 5;
    int wm = wid & 1;        // 0..1 -> 32-row block
    int wn = wid >> 1;       // 0..3 -> 32-col block
    int blockRow = blockIdx.x * 64;
    int c0 = blockIdx.y * 128;

    if constexpr (MODE == 1) {
        if (t < 256) { s_a1[t] = g_a1[t]; s_c1[t] = g_c1[t]; }
        __syncthreads();
    }

    // staging maps (256 threads; A: 64x64, B: 64x128 per chunk)
    int arow = t >> 2;             // 0..63
    int ac0  = (t & 3) * 16;       // 0,16,32,48
    int bkr  = t >> 2;             // 0..63
    int bn0  = (t & 3) * 32;       // 0,32,64,96

    // mma lane addressing
    int a_r  = wm * 32 + (lane & 15);
    int a_kh = (lane >> 4) * 8;
    uint32_t swa = (uint32_t)((a_r & 7) << 4);
    int bl   = lane & 15;
    int b_k7 = bl & 7;
    int b_kh = ((bl >> 3) & 1) * 8;
    uint32_t nboff[4];
#pragma unroll
    for (int ni = 0; ni < 4; ni++)
        nboff[ni] = ((uint32_t)((wn * 32 + ni * 8) * 2)) ^ ((uint32_t)(b_k7 << 4));

    float acc[2][4][4];
#pragma unroll
    for (int mi = 0; mi < 2; mi++)
#pragma unroll
        for (int ni = 0; ni < 4; ni++)
#pragma unroll
            for (int j = 0; j < 4; j++) acc[mi][ni][j] = 0.f;

    float4 hA[4];   // A prefetch

    auto LOADA = [&](int kc) {
        size_t r = (size_t)(blockRow + arow);
        int kg = kc * 64 + ac0;
#pragma unroll
        for (int q = 0; q < 4; q++) {
            if constexpr (MODE == 0)
                hA[q] = *(const float4*)&g_pre[r * 128 + kg + q * 4];
            else
                hA[q] = *(const float4*)&g_t1[r * 256 + kg + q * 4];
        }
    };
    auto STORE = [&](int s, int kc) {
        char* Ah = smem + s * STAGE_BYTES;
        char* Al = Ah + 8192;
        char* Bh = Ah + 16384;
        char* Bl = Ah + 32768;
#pragma unroll
        for (int q = 0; q < 4; q++) {
            int cl = ac0 + q * 4;
            float4 a = hA[q];
            if constexpr (MODE == 1) {
                int kg = kc * 64 + cl;
                float4 sc = *(const float4*)&s_a1[kg];
                float4 sh = *(const float4*)&s_c1[kg];
                a.x = fmaxf(fmaf(a.x, sc.x, sh.x), 0.f);
                a.y = fmaxf(fmaf(a.y, sc.y, sh.y), 0.f);
                a.z = fmaxf(fmaf(a.z, sc.z, sh.z), 0.f);
                a.w = fmaxf(fmaf(a.w, sc.w, sh.w), 0.f);
            }
            uint32_t h01, l01, h23, l23;
            split2(a.x, a.y, h01, l01);
            split2(a.z, a.w, h23, l23);
            uint32_t off = sw128((uint32_t)(arow * 128 + cl * 2));
            *(uint2*)(Ah + off) = make_uint2(h01, h23);
            *(uint2*)(Al + off) = make_uint2(l01, l23);
        }
        // B: plain copies from pre-split bf16 hi/lo (8B each)
        size_t wrow = (size_t)(kc * 64 + bkr) * NCOL + c0;
#pragma unroll
        for (int q = 0; q < 8; q++) {
            int n = bn0 + q * 4;
            uint2 hv = *(const uint2*)&Wh[wrow + n];
            uint2 lv = *(const uint2*)&Wl[wrow + n];
            uint32_t off = (uint32_t)(bkr * 256) +
                           (((uint32_t)(n * 2)) ^ ((uint32_t)((bkr & 7) << 4)));
            *(uint2*)(Bh + off) = hv;
            *(uint2*)(Bl + off) = lv;
        }
    };
    auto MMA = [&](int s) {
        uint32_t Au   = sbase + s * STAGE_BYTES;
        uint32_t Alou = Au + 8192;
        uint32_t Bu   = Au + 16384;
        uint32_t Blou = Au + 32768;
#pragma unroll
        for (int term = 0; term < 3; term++) {
            uint32_t Ab = (term == 2) ? Alou : Au;
            uint32_t Bb = (term == 1) ? Blou : Bu;
#pragma unroll
            for (int kk = 0; kk < 4; kk++) {
                int k0 = kk * 16;
                uint32_t a[2][4];
                uint32_t b[4][2];
                uint32_t kA = (((uint32_t)((k0 + a_kh) * 2)) ^ swa);
#pragma unroll
                for (int mi = 0; mi < 2; mi++)
                    ldsm_x4(a[mi], Ab + (uint32_t)((a_r + mi * 16) * 128) + kA);
                uint32_t kB = (uint32_t)((k0 + b_kh + b_k7) * 256);
#pragma unroll
                for (int ni = 0; ni < 4; ni++)
                    ldsm_x2_t(b[ni], Bb + kB + nboff[ni]);
#pragma unroll
                for (int mi = 0; mi < 2; mi++)
#pragma unroll
                    for (int ni = 0; ni < 4; ni++)
                        mma16816(acc[mi][ni], a[mi], b[ni]);
            }
        }
    };

    // ---- pipeline ----
    LOADA(0);
    STORE(0, 0);
    __syncthreads();
#pragma unroll
    for (int kc = 0; kc < NCHUNK; kc++) {
        if (kc + 1 < NCHUNK) LOADA(kc + 1);
        MMA(kc & 1);
        if (kc + 1 < NCHUNK) STORE((kc + 1) & 1, kc + 1);
        __syncthreads();
    }

    // ---- epilogue: bias add, store C, fused column stats ----
    float* s_s = (float*)smem;         // 128 floats (stage 0 free after last MMA)
    float* s_q = (float*)smem + 128;
    if (t < 128) { s_s[t] = 0.f; s_q[t] = 0.f; }
    __syncthreads();

    float* Cout = (MODE == 0) ? g_t1 : g_hc;
    int gidl = lane >> 2, tq = lane & 3;
    int colbase = wn * 32 + tq * 2;
    float2 bv[4];
#pragma unroll
    for (int ni = 0; ni < 4; ni++)
        bv[ni] = *(const float2*)&bias[c0 + colbase + ni * 8];

    float ssum[4][2] = {}, qsum[4][2] = {};
#pragma unroll
    for (int mi = 0; mi < 2; mi++) {
        int r0 = blockRow + wm * 32 + mi * 16 + gidl;
        int r1 = r0 + 8;
        bool ok0 = r0 < NN, ok1 = r1 < NN;
#pragma unroll
        for (int ni = 0; ni < 4; ni++) {
            float v0 = acc[mi][ni][0] + bv[ni].x;
            float v1 = acc[mi][ni][1] + bv[ni].y;
            float v2 = acc[mi][ni][2] + bv[ni].x;
            float v3 = acc[mi][ni][3] + bv[ni].y;
            int col = c0 + colbase + ni * 8;
            if (ok0) {
                *(float2*)&Cout[(size_t)r0 * NCOL + col] = make_float2(v0, v1);
                ssum[ni][0] += v0; qsum[ni][0] += v0 * v0;
                ssum[ni][1] += v1; qsum[ni][1] += v1 * v1;
            }
            if (ok1) {
                *(float2*)&Cout[(size_t)r1 * NCOL + col] = make_float2(v2, v3);
                ssum[ni][0] += v2; qsum[ni][0] += v2 * v2;
                ssum[ni][1] += v3; qsum[ni][1] += v3 * v3;
            }
        }
    }
#pragma unroll
    for (int ni = 0; ni < 4; ni++) {
        int cl = colbase + ni * 8;
        atomicAdd(&s_s[cl], ssum[ni][0]);
        atomicAdd(&s_s[cl + 1], ssum[ni][1]);
        atomicAdd(&s_q[cl], qsum[ni][0]);
        atomicAdd(&s_q[cl + 1], qsum[ni][1]);
    }
    __syncthreads();
    if (t < 128) {
        float* Sg = (MODE == 0) ? g_sum1 : g_sum2;
        float* Qg = (MODE == 0) ? g_sq1 : g_sq2;
        atomicAdd(&Sg[c0 + t], s_s[t]);
        atomicAdd(&Qg[c0 + t], s_q[t]);
    }
}

// ---------------- finalize BN affine: a = g/sqrt(var+eps), b = beta - mean*a --------
template <int WHICH>
__global__ void finalize_kernel(const float* __restrict__ gamma,
                                const float* __restrict__ beta) {
    constexpr int C = (WHICH == 0) ? 256 : 128;
    int c = threadIdx.x;
    if (c >= C) return;
    float s = (WHICH == 0) ? g_sum1[c] : g_sum2[c];
    float q = (WHICH == 0) ? g_sq1[c]  : g_sq2[c];
    float mean = s * (1.f / NN);
    float var  = q * (1.f / NN) - mean * mean;
    float inv  = rsqrtf(var + 1e-5f);
    float a = gamma[c] * inv;
    float b = beta[c] - mean * a;
    if (WHICH == 0) { g_a1[c] = a; g_c1[c] = b; }
    else            { g_a2[c] = a; g_c2[c] = b; }
}

// ---------------- apply final BN (no relu), write d_out -----------
__global__ void bnapply_kernel(float* __restrict__ dst) {
    int gid = blockIdx.x * blockDim.x + threadIdx.x;
    int node = gid >> 5;
    if (node >= NN) return;
    int c = (gid & 31) * 4;
    float4 v = *(const float4*)&g_hc[(size_t)node * 128 + c];
    float4 a = *(const float4*)&g_a2[c];
    float4 b = *(const float4*)&g_c2[c];
    float4 o;
    o.x = v.x * a.x + b.x; o.y = v.y * a.y + b.y;
    o.z = v.z * a.z + b.z; o.w = v.w * a.w + b.w;
    *(float4*)&dst[(size_t)node * 128 + c] = o;
}

// ---------------- launch ----------------
extern "C" void kernel_launch(void* const* d_in, const int* in_sizes, int n_in,
                              void* d_out, int out_size) {
    const int*   x    = (const int*)d_in[0];
    const int*   z    = (const int*)d_in[1];
    const int*   ei   = (const int*)d_in[2];
    const int*   ea   = (const int*)d_in[3];
    const float* atom = (const float*)d_in[4];
    const float* zemb = (const float*)d_in[5];
    const float* bond = (const float*)d_in[6];
    const float* eps  = (const float*)d_in[7];
    const float* W1   = (const float*)d_in[8];
    const float* b1   = (const float*)d_in[9];
    const float* g1   = (const float*)d_in[10];
    const float* be1  = (const float*)d_in[11];
    const float* W2   = (const float*)d_in[12];
    const float* b2   = (const float*)d_in[13];
    const float* bng  = (const float*)d_in[14];
    const float* bnb  = (const float*)d_in[15];
    float* out = (float*)d_out;

    static bool attr_done = false;
    if (!attr_done) {
        cudaFuncSetAttribute(gemm_mma<0>, cudaFuncAttributeMaxDynamicSharedMemorySize, GEMM_SMEM);
        cudaFuncSetAttribute(gemm_mma<1>, cudaFuncAttributeMaxDynamicSharedMemorySize, GEMM_SMEM);
        attr_done = true;
    }

    const int NODE_BLKS = (NN * 32 + 255) / 256;   // 12500
    const int EDGE_BLKS = (EE + 255) / 256;        // 6250
    const int NB        = (NN + 255) / 256;        // 391

    embed_kernel<<<NODE_BLKS, 256>>>(x, z, atom, zemb);
    prep_w<<<256, 256>>>(W1, W2);

    // CSR build (edge_index is the same for both layers)
    hist_kernel<<<EDGE_BLKS, 256>>>(ei);
    scan1_kernel<<<NB, 256>>>();
    scan2_kernel<<<1, 32>>>(NB);
    scan3_kernel<<<NB, 256>>>();
    scatter_kernel<<<EDGE_BLKS, 256>>>(ei, ea);

    for (int l = 0; l < 2; l++) {
        if (l == 0)
            agg_kernel<0><<<NODE_BLKS, 256>>>(bond + (size_t)l * 3 * 6 * 128, eps + l);
        else
            agg_kernel<1><<<NODE_BLKS, 256>>>(bond + (size_t)l * 3 * 6 * 128, eps + l);
        gemm_mma<0><<<dim3(NPAD / 64, 2), 256, GEMM_SMEM>>>(b1 + l * 256, l);
        finalize_kernel<0><<<1, 256>>>(g1 + l * 256, be1 + l * 256);
        gemm_mma<1><<<dim3(NPAD / 64, 1), 256, GEMM_SMEM>>>(b2 + l * 128, l);
        finalize_kernel<1><<<1, 128>>>(bng + l * 128, bnb + l * 128);
    }
    bnapply_kernel<<<NODE_BLKS, 256>>>(out);
}